// round 5
// baseline (speedup 1.0000x reference)
#include <cuda_runtime.h>
#include <math.h>
#include <float.h>

#define D        256
#define BM       32
#define BN       128
#define DK       64
#define NSPLIT   4
#define THREADS  128
#define KS_STRIDE 68    // DK + 4 pad
#define QS_STRIDE 260   // D + 4 pad
#define PS_STRIDE 132   // BN + 4 pad
#define MAXB     4096

// Scratch for split-K partials (no allocations allowed -> device globals)
__device__ float g_Opart[(size_t)NSPLIT * MAXB * D];   // unnormalized partial O
__device__ float g_m[NSPLIT * MAXB];
__device__ float g_l[NSPLIT * MAXB];

extern "C" __global__ void __launch_bounds__(THREADS)
attn_kernel(const float* __restrict__ Qg, const float* __restrict__ Kn,
            const float* __restrict__ Vn, const float* __restrict__ Kc,
            const float* __restrict__ Vc, const int* __restrict__ old_ptr,
            int Bq)
{
    extern __shared__ float smf[];
    float* Qs   = smf;                       // BM x QS_STRIDE
    float* Ks   = Qs + BM * QS_STRIDE;       // BN x KS_STRIDE
    float* Ps   = Ks + BN * KS_STRIDE;       // BM x PS_STRIDE
    float* m_sm = Ps + BM * PS_STRIDE;       // BM
    float* l_sm = m_sm + BM;                 // BM
    float* osc  = l_sm + BM;                 // BM

    const int t    = threadIdx.x;
    const int lane = t & 31;
    const int w    = t >> 5;       // warp id, owns query rows w*8 .. w*8+7
    const int sq   = t >> 4;       // S-phase row group (rows sq*4 .. +3)
    const int sk   = t & 15;       // S-phase key lane

    const int old = *old_ptr;
    const int nsz = old + Bq;
    const int q0  = blockIdx.x * BM;
    const int split = blockIdx.y;

    // key range for this split, tile-aligned
    int chunk = ((nsz + NSPLIT * BN - 1) / (NSPLIT * BN)) * BN;
    int kbeg  = split * chunk;
    int kend  = min(kbeg + chunk, nsz);

    // ---- load Q tile (pre-scaled by 1/sqrt(D)) ----
    const float qscale = 1.0f / sqrtf((float)D);   // exact 1/16 for D=256
    for (int i = t; i < BM * (D / 4); i += THREADS) {
        int r  = i / (D / 4);
        int c4 = (i % (D / 4)) * 4;
        float4 v = make_float4(0.f, 0.f, 0.f, 0.f);
        if (q0 + r < Bq)
            v = *(const float4*)(Qg + (size_t)(q0 + r) * D + c4);
        float* dst = Qs + r * QS_STRIDE + c4;
        dst[0] = v.x * qscale; dst[1] = v.y * qscale;
        dst[2] = v.z * qscale; dst[3] = v.w * qscale;
    }
    if (t < BM) { m_sm[t] = -FLT_MAX; l_sm[t] = 0.f; osc[t] = 1.f; }

    // O accumulators: 8 rows x 8 dims (vd = lane*8 .. +7)
    float4 Oa[8], Ob[8];
    #pragma unroll
    for (int i = 0; i < 8; i++) {
        Oa[i] = make_float4(0.f, 0.f, 0.f, 0.f);
        Ob[i] = make_float4(0.f, 0.f, 0.f, 0.f);
    }

    for (int kb = kbeg; kb < kend; kb += BN) {
        // ================= S = Q * K^T =================
        float s[4][8];
        #pragma unroll
        for (int i = 0; i < 4; i++)
            #pragma unroll
            for (int j = 0; j < 8; j++) s[i][j] = 0.f;

        for (int c = 0; c < D / DK; c++) {
            const int d0 = c * DK;
            __syncthreads();
            // stage K[kb..kb+BN)[d0..d0+DK) -> Ks  (coalesced LDG.128)
            #pragma unroll
            for (int p = 0; p < 16; p++) {
                int key = (t >> 4) + p * 8;
                int col = (t & 15) * 4;
                int kg  = kb + key;
                float4 v = make_float4(0.f, 0.f, 0.f, 0.f);
                if (kg < nsz) {
                    const float* src = (kg < old) ? (Kc + (size_t)kg * D)
                                                  : (Kn + (size_t)(kg - old) * D);
                    v = *(const float4*)(src + d0 + col);
                }
                *(float4*)(Ks + key * KS_STRIDE + col) = v;
            }
            __syncthreads();

            #pragma unroll 2
            for (int dd = 0; dd < DK; dd += 4) {
                float4 qv[4], kv[8];
                #pragma unroll
                for (int i = 0; i < 4; i++)
                    qv[i] = *(float4*)(Qs + (sq * 4 + i) * QS_STRIDE + d0 + dd);
                #pragma unroll
                for (int j = 0; j < 8; j++)
                    kv[j] = *(float4*)(Ks + (sk + 16 * j) * KS_STRIDE + dd);
                #pragma unroll
                for (int i = 0; i < 4; i++)
                    #pragma unroll
                    for (int j = 0; j < 8; j++)
                        s[i][j] += qv[i].x * kv[j].x + qv[i].y * kv[j].y
                                 + qv[i].z * kv[j].z + qv[i].w * kv[j].w;
            }
        }

        // ================= online softmax (per warp, half-warp reduce) =================
        #pragma unroll
        for (int i = 0; i < 4; i++) {
            const int R  = sq * 4 + i;
            const int qg = q0 + R;
            float lm = -FLT_MAX;
            #pragma unroll
            for (int j = 0; j < 8; j++) {
                int kg = kb + sk + 16 * j;
                bool ok = (kg <= old + qg) && (kg < nsz);
                s[i][j] = ok ? s[i][j] : -FLT_MAX;
                lm = fmaxf(lm, s[i][j]);
            }
            #pragma unroll
            for (int x = 1; x < 16; x <<= 1)
                lm = fmaxf(lm, __shfl_xor_sync(0xffffffffu, lm, x));
            float mo = m_sm[R];
            float mn = fmaxf(mo, lm);
            float rs = 0.f;
            #pragma unroll
            for (int j = 0; j < 8; j++) {
                float p = (s[i][j] > -FLT_MAX) ? __expf(s[i][j] - mn) : 0.f;
                s[i][j] = p;
                rs += p;
            }
            #pragma unroll
            for (int x = 1; x < 16; x <<= 1)
                rs += __shfl_xor_sync(0xffffffffu, rs, x);
            if (sk == 0) {
                float sc = __expf(mo - mn);   // 0 on first tile, 1 if tile masked
                l_sm[R] = l_sm[R] * sc + rs;
                m_sm[R] = mn;
                osc[R]  = sc;
            }
            #pragma unroll
            for (int j = 0; j < 8; j++)
                Ps[R * PS_STRIDE + sk + 16 * j] = s[i][j];
        }
        __syncwarp();

        // ================= O = O*scale + P * V =================
        #pragma unroll
        for (int i = 0; i < 8; i++) {
            float sc = osc[w * 8 + i];
            Oa[i].x *= sc; Oa[i].y *= sc; Oa[i].z *= sc; Oa[i].w *= sc;
            Ob[i].x *= sc; Ob[i].y *= sc; Ob[i].z *= sc; Ob[i].w *= sc;
        }
        #pragma unroll 2
        for (int kk = 0; kk < BN; kk++) {
            int kg = kb + kk;
            if (kg >= nsz) break;                 // uniform across CTA
            const float* vr = (kg < old) ? (Vc + (size_t)kg * D)
                                         : (Vn + (size_t)(kg - old) * D);
            float4 va = *(const float4*)(vr + lane * 8);
            float4 vb = *(const float4*)(vr + lane * 8 + 4);
            #pragma unroll
            for (int i = 0; i < 8; i++) {
                float p = Ps[(w * 8 + i) * PS_STRIDE + kk];
                Oa[i].x += p * va.x; Oa[i].y += p * va.y;
                Oa[i].z += p * va.z; Oa[i].w += p * va.w;
                Ob[i].x += p * vb.x; Ob[i].y += p * vb.y;
                Ob[i].z += p * vb.z; Ob[i].w += p * vb.w;
            }
        }
    }

    __syncthreads();
    // ---- write split partials ----
    size_t base = ((size_t)split * MAXB + q0) * D;
    #pragma unroll
    for (int i = 0; i < 8; i++) {
        int r = w * 8 + i;
        if (q0 + r < Bq) {
            float* dst = g_Opart + base + (size_t)r * D + lane * 8;
            *(float4*)dst       = Oa[i];
            *(float4*)(dst + 4) = Ob[i];
        }
    }
    if (t < BM && q0 + t < Bq) {
        g_m[split * MAXB + q0 + t] = m_sm[t];
        g_l[split * MAXB + q0 + t] = l_sm[t];
    }
}

extern "C" __global__ void combine_kernel(float* __restrict__ out, int Bq)
{
    int idx = blockIdx.x * blockDim.x + threadIdx.x;
    if (idx >= Bq * D) return;
    int q  = idx / D;
    int vd = idx - q * D;

    float M = -FLT_MAX;
    #pragma unroll
    for (int s = 0; s < NSPLIT; s++)
        M = fmaxf(M, g_m[s * MAXB + q]);

    float num = 0.f, den = 0.f;
    #pragma unroll
    for (int s = 0; s < NSPLIT; s++) {
        float wv = __expf(g_m[s * MAXB + q] - M);   // 0 for empty splits
        den += wv * g_l[s * MAXB + q];
        num += wv * g_Opart[((size_t)s * MAXB + q) * D + vd];
    }
    out[idx] = num / den;
}

extern "C" void kernel_launch(void* const* d_in, const int* in_sizes, int n_in,
                              void* d_out, int out_size)
{
    const float* q   = (const float*)d_in[0];
    const float* k   = (const float*)d_in[1];
    const float* v   = (const float*)d_in[2];
    const float* Kc  = (const float*)d_in[3];
    const float* Vc  = (const float*)d_in[4];
    const int*   oldp = (const int*)d_in[5];
    int Bq = in_sizes[0] / D;   // 2048

    size_t smem = (size_t)(BM * QS_STRIDE + BN * KS_STRIDE + BM * PS_STRIDE + 3 * BM)
                  * sizeof(float);
    cudaFuncSetAttribute((const void*)attn_kernel,
                         cudaFuncAttributeMaxDynamicSharedMemorySize, (int)smem);

    dim3 grid(Bq / BM, NSPLIT);
    attn_kernel<<<grid, THREADS, smem>>>(q, k, v, Kc, Vc, oldp, Bq);
    combine_kernel<<<(Bq * D + 255) / 256, 256>>>((float*)d_out, Bq);
}

// round 6
// speedup vs baseline: 2.5157x; 2.5157x over previous
#include <cuda_runtime.h>
#include <cuda_bf16.h>
#include <math.h>
#include <float.h>

#define D      256
#define BM     32
#define BN     64
#define NSPLIT 4
#define NTHR   256
#define QSTR   264
#define KSTR   72
#define MAXB   2048

#define OFF_QHI 0
#define OFF_QLO 16896
#define OFF_KVH 33792
#define OFF_KVL 43008
#define OFF_PHI 52224
#define OFF_PLO 56832
#define OFF_FLT 61440
#define SMEM_BYTES 62848

__device__ float g_Opart[(size_t)NSPLIT * MAXB * D];
__device__ float g_m[NSPLIT * MAXB];
__device__ float g_l[NSPLIT * MAXB];

__device__ __forceinline__ float bfr(float x) {
    return __bfloat162float(__float2bfloat16(x));
}
__device__ __forceinline__ unsigned pack_bf2(float a, float b) {
    __nv_bfloat162 t = __floats2bfloat162_rn(a, b);
    return *reinterpret_cast<unsigned*>(&t);
}
__device__ __forceinline__ void mma_bf16(float* c, unsigned a0, unsigned a1,
                                         unsigned a2, unsigned a3,
                                         unsigned b0, unsigned b1) {
    asm volatile(
        "mma.sync.aligned.m16n8k16.row.col.f32.bf16.bf16.f32 "
        "{%0,%1,%2,%3}, {%4,%5,%6,%7}, {%8,%9}, {%0,%1,%2,%3};\n"
        : "+f"(c[0]), "+f"(c[1]), "+f"(c[2]), "+f"(c[3])
        : "r"(a0), "r"(a1), "r"(a2), "r"(a3), "r"(b0), "r"(b1));
}
__device__ __forceinline__ void ldsm_x4(unsigned& r0, unsigned& r1, unsigned& r2,
                                        unsigned& r3, unsigned a) {
    asm volatile("ldmatrix.sync.aligned.m8n8.x4.shared.b16 {%0,%1,%2,%3}, [%4];"
                 : "=r"(r0), "=r"(r1), "=r"(r2), "=r"(r3) : "r"(a));
}
__device__ __forceinline__ void ldsm_x2(unsigned& r0, unsigned& r1, unsigned a) {
    asm volatile("ldmatrix.sync.aligned.m8n8.x2.shared.b16 {%0,%1}, [%2];"
                 : "=r"(r0), "=r"(r1) : "r"(a));
}
__device__ __forceinline__ void ldsm_x2t(unsigned& r0, unsigned& r1, unsigned a) {
    asm volatile("ldmatrix.sync.aligned.m8n8.x2.trans.shared.b16 {%0,%1}, [%2];"
                 : "=r"(r0), "=r"(r1) : "r"(a));
}

// stage 64 keys x 64 dims (chunk dc) fp32 -> bf16 hi/lo tiles
__device__ __forceinline__ void stage_tile(const float* __restrict__ cache,
                                           const float* __restrict__ fresh,
                                           int kb, int dc, int old, int nsz, int t,
                                           __nv_bfloat16* Hh, __nv_bfloat16* Hl) {
    #pragma unroll
    for (int p = 0; p < 4; p++) {
        int key = (t >> 4) + p * 16;
        int d4  = (t & 15) * 4;
        int kg  = kb + key;
        float4 v = make_float4(0.f, 0.f, 0.f, 0.f);
        if (kg < nsz) {
            const float* src = (kg < old) ? (cache + (size_t)kg * D)
                                          : (fresh + (size_t)(kg - old) * D);
            v = *(const float4*)(src + dc * 64 + d4);
        }
        float hx = bfr(v.x), hy = bfr(v.y), hz = bfr(v.z), hw = bfr(v.w);
        *(uint2*)&Hh[key * KSTR + d4] = make_uint2(pack_bf2(hx, hy), pack_bf2(hz, hw));
        *(uint2*)&Hl[key * KSTR + d4] = make_uint2(pack_bf2(v.x - hx, v.y - hy),
                                                   pack_bf2(v.z - hz, v.w - hw));
    }
}

extern "C" __global__ void __launch_bounds__(NTHR, 2)
attn_mma(const float* __restrict__ Qg, const float* __restrict__ Kn,
         const float* __restrict__ Vn, const float* __restrict__ Kc,
         const float* __restrict__ Vc, const int* __restrict__ old_ptr, int Bq)
{
    extern __shared__ char smraw[];
    __nv_bfloat16* Qhi = (__nv_bfloat16*)(smraw + OFF_QHI);
    __nv_bfloat16* Qlo = (__nv_bfloat16*)(smraw + OFF_QLO);
    __nv_bfloat16* KVh = (__nv_bfloat16*)(smraw + OFF_KVH);
    __nv_bfloat16* KVl = (__nv_bfloat16*)(smraw + OFF_KVL);
    __nv_bfloat16* Phi = (__nv_bfloat16*)(smraw + OFF_PHI);
    __nv_bfloat16* Plo = (__nv_bfloat16*)(smraw + OFF_PLO);
    float* m_s  = (float*)(smraw + OFF_FLT);
    float* l_s  = m_s + 32;
    float* oscs = l_s + 32;
    float* redm = oscs + 32;   // [32][4]
    float* reds = redm + 128;  // [32][4]

    const unsigned smb = (unsigned)__cvta_generic_to_shared(smraw);
    const int t    = threadIdx.x;
    const int lane = t & 31;
    const int w    = t >> 5;
    const int grp  = lane >> 2;
    const int qd   = lane & 3;
    const int mg   = w & 1;
    const int ng   = w >> 1;

    const int old = *old_ptr;
    const int nsz = old + Bq;
    const int q0  = blockIdx.x * BM;
    const int split = blockIdx.y;

    const int kmax  = min(nsz, old + q0 + BM);
    const int chunk = ((kmax + NSPLIT * BN - 1) / (NSPLIT * BN)) * BN;
    const int kbeg  = split * chunk;
    const int kend  = min(kbeg + chunk, kmax);

    // stage Q (pre-scaled 1/16), hi/lo split
    #pragma unroll
    for (int p = 0; p < 8; p++) {
        int idx = t + NTHR * p;
        int r   = idx >> 6;
        int c4  = (idx & 63) * 4;
        float4 v = *(const float4*)(Qg + (size_t)(q0 + r) * D + c4);
        v.x *= 0.0625f; v.y *= 0.0625f; v.z *= 0.0625f; v.w *= 0.0625f;
        float hx = bfr(v.x), hy = bfr(v.y), hz = bfr(v.z), hw = bfr(v.w);
        *(uint2*)&Qhi[r * QSTR + c4] = make_uint2(pack_bf2(hx, hy), pack_bf2(hz, hw));
        *(uint2*)&Qlo[r * QSTR + c4] = make_uint2(pack_bf2(v.x - hx, v.y - hy),
                                                  pack_bf2(v.z - hz, v.w - hw));
    }
    if (t < 32) { m_s[t] = -FLT_MAX; l_s[t] = 0.f; }

    float Of[4][2][4];
    #pragma unroll
    for (int a = 0; a < 4; a++)
        #pragma unroll
        for (int b = 0; b < 2; b++)
            #pragma unroll
            for (int c = 0; c < 4; c++) Of[a][b][c] = 0.f;
    __syncthreads();

    for (int kb = kbeg; kb < kend; kb += BN) {
        // ---------- S = Q K^T ----------
        float S[2][4];
        #pragma unroll
        for (int nt = 0; nt < 2; nt++)
            #pragma unroll
            for (int i = 0; i < 4; i++) S[nt][i] = 0.f;

        for (int dc = 0; dc < 4; dc++) {
            __syncthreads();
            stage_tile(Kc, Kn, kb, dc, old, nsz, t, KVh, KVl);
            __syncthreads();
            #pragma unroll
            for (int ks = 0; ks < 4; ks++) {
                int arow = 16 * mg + (lane & 7) + 8 * ((lane >> 3) & 1);
                int acol = dc * 64 + ks * 16 + 8 * (lane >> 4);
                unsigned aq = smb + OFF_QHI + (unsigned)(arow * QSTR + acol) * 2u;
                unsigned ah0, ah1, ah2, ah3, al0, al1, al2, al3;
                ldsm_x4(ah0, ah1, ah2, ah3, aq);
                ldsm_x4(al0, al1, al2, al3, aq + (OFF_QLO - OFF_QHI));
                #pragma unroll
                for (int nt = 0; nt < 2; nt++) {
                    int bkey = 16 * ng + 8 * nt + (lane & 7);
                    int bcol = ks * 16 + 8 * ((lane >> 3) & 1);
                    unsigned ba = smb + OFF_KVH + (unsigned)(bkey * KSTR + bcol) * 2u;
                    unsigned bh0, bh1, bl0, bl1;
                    ldsm_x2(bh0, bh1, ba);
                    ldsm_x2(bl0, bl1, ba + (OFF_KVL - OFF_KVH));
                    mma_bf16(S[nt], ah0, ah1, ah2, ah3, bh0, bh1);
                    mma_bf16(S[nt], ah0, ah1, ah2, ah3, bl0, bl1);
                    mma_bf16(S[nt], al0, al1, al2, al3, bh0, bh1);
                }
            }
        }

        // ---------- online softmax ----------
        const int R0 = 16 * mg + grp, R1 = R0 + 8;
        const int lim0 = old + q0 + R0, lim1 = old + q0 + R1;
        float mx0 = -FLT_MAX, mx1 = -FLT_MAX;
        #pragma unroll
        for (int nt = 0; nt < 2; nt++) {
            int kcb = kb + 16 * ng + 8 * nt + 2 * qd;
            mx0 = fmaxf(mx0, fmaxf((kcb     <= lim0) ? S[nt][0] : -FLT_MAX,
                                   (kcb + 1 <= lim0) ? S[nt][1] : -FLT_MAX));
            mx1 = fmaxf(mx1, fmaxf((kcb     <= lim1) ? S[nt][2] : -FLT_MAX,
                                   (kcb + 1 <= lim1) ? S[nt][3] : -FLT_MAX));
        }
        mx0 = fmaxf(mx0, __shfl_xor_sync(0xffffffffu, mx0, 1));
        mx0 = fmaxf(mx0, __shfl_xor_sync(0xffffffffu, mx0, 2));
        mx1 = fmaxf(mx1, __shfl_xor_sync(0xffffffffu, mx1, 1));
        mx1 = fmaxf(mx1, __shfl_xor_sync(0xffffffffu, mx1, 2));
        if (qd == 0) { redm[R0 * 4 + ng] = mx0; redm[R1 * 4 + ng] = mx1; }
        __syncthreads();

        float mf0 = m_s[R0], mf1 = m_s[R1];
        #pragma unroll
        for (int g = 0; g < 4; g++) {
            mf0 = fmaxf(mf0, redm[R0 * 4 + g]);
            mf1 = fmaxf(mf1, redm[R1 * 4 + g]);
        }
        float sum0 = 0.f, sum1 = 0.f;
        #pragma unroll
        for (int nt = 0; nt < 2; nt++) {
            int kcb = kb + 16 * ng + 8 * nt + 2 * qd;
            float p0 = (kcb     <= lim0) ? __expf(S[nt][0] - mf0) : 0.f;
            float p1 = (kcb + 1 <= lim0) ? __expf(S[nt][1] - mf0) : 0.f;
            float p2 = (kcb     <= lim1) ? __expf(S[nt][2] - mf1) : 0.f;
            float p3 = (kcb + 1 <= lim1) ? __expf(S[nt][3] - mf1) : 0.f;
            sum0 += p0 + p1; sum1 += p2 + p3;
            float h0 = bfr(p0), h1 = bfr(p1), h2 = bfr(p2), h3 = bfr(p3);
            int kc = 16 * ng + 8 * nt + 2 * qd;
            *(unsigned*)&Phi[R0 * KSTR + kc] = pack_bf2(h0, h1);
            *(unsigned*)&Phi[R1 * KSTR + kc] = pack_bf2(h2, h3);
            *(unsigned*)&Plo[R0 * KSTR + kc] = pack_bf2(p0 - h0, p1 - h1);
            *(unsigned*)&Plo[R1 * KSTR + kc] = pack_bf2(p2 - h2, p3 - h3);
        }
        sum0 += __shfl_xor_sync(0xffffffffu, sum0, 1);
        sum0 += __shfl_xor_sync(0xffffffffu, sum0, 2);
        sum1 += __shfl_xor_sync(0xffffffffu, sum1, 1);
        sum1 += __shfl_xor_sync(0xffffffffu, sum1, 2);
        if (qd == 0) { reds[R0 * 4 + ng] = sum0; reds[R1 * 4 + ng] = sum1; }
        __syncthreads();

        if (t < 32) {
            float mo = m_s[t], mf = mo;
            #pragma unroll
            for (int g = 0; g < 4; g++) mf = fmaxf(mf, redm[t * 4 + g]);
            float sc = __expf(mo - mf);
            l_s[t] = l_s[t] * sc + reds[t * 4] + reds[t * 4 + 1]
                                 + reds[t * 4 + 2] + reds[t * 4 + 3];
            m_s[t] = mf;
            oscs[t] = sc;
        }
        __syncthreads();

        {
            float s0 = oscs[grp],      s1 = oscs[grp + 8];
            float s2 = oscs[grp + 16], s3 = oscs[grp + 24];
            #pragma unroll
            for (int dcx = 0; dcx < 4; dcx++) {
                Of[dcx][0][0] *= s0; Of[dcx][0][1] *= s0;
                Of[dcx][0][2] *= s1; Of[dcx][0][3] *= s1;
                Of[dcx][1][0] *= s2; Of[dcx][1][1] *= s2;
                Of[dcx][1][2] *= s3; Of[dcx][1][3] *= s3;
            }
        }

        // ---------- O += P V ----------
        #pragma unroll
        for (int dc = 0; dc < 4; dc++) {
            __syncthreads();
            stage_tile(Vc, Vn, kb, dc, old, nsz, t, KVh, KVl);
            __syncthreads();
            #pragma unroll
            for (int kk = 0; kk < 4; kk++) {
                int bkey = kk * 16 + (lane & 7) + 8 * ((lane >> 3) & 1);
                unsigned ba = smb + OFF_KVH + (unsigned)(bkey * KSTR + w * 8) * 2u;
                unsigned bh0, bh1, bl0, bl1;
                ldsm_x2t(bh0, bh1, ba);
                ldsm_x2t(bl0, bl1, ba + (OFF_KVL - OFF_KVH));
                #pragma unroll
                for (int mt = 0; mt < 2; mt++) {
                    int arow = 16 * mt + (lane & 7) + 8 * ((lane >> 3) & 1);
                    int acol = kk * 16 + 8 * (lane >> 4);
                    unsigned pa = smb + OFF_PHI + (unsigned)(arow * KSTR + acol) * 2u;
                    unsigned ph0, ph1, ph2, ph3, pl0, pl1, pl2, pl3;
                    ldsm_x4(ph0, ph1, ph2, ph3, pa);
                    ldsm_x4(pl0, pl1, pl2, pl3, pa + (OFF_PLO - OFF_PHI));
                    mma_bf16(Of[dc][mt], ph0, ph1, ph2, ph3, bh0, bh1);
                    mma_bf16(Of[dc][mt], ph0, ph1, ph2, ph3, bl0, bl1);
                    mma_bf16(Of[dc][mt], pl0, pl1, pl2, pl3, bh0, bh1);
                }
            }
        }
    }

    __syncthreads();
    size_t obase = ((size_t)split * MAXB + q0) * D;
    #pragma unroll
    for (int dc = 0; dc < 4; dc++) {
        int d = dc * 64 + w * 8 + 2 * qd;
        #pragma unroll
        for (int mt = 0; mt < 2; mt++) {
            int r = 16 * mt + grp;
            *(float2*)&g_Opart[obase + (size_t)r * D + d] =
                make_float2(Of[dc][mt][0], Of[dc][mt][1]);
            *(float2*)&g_Opart[obase + (size_t)(r + 8) * D + d] =
                make_float2(Of[dc][mt][2], Of[dc][mt][3]);
        }
    }
    if (t < 32) {
        g_m[split * MAXB + q0 + t] = m_s[t];
        g_l[split * MAXB + q0 + t] = l_s[t];
    }
}

extern "C" __global__ void combine_kernel(float* __restrict__ out, int Bq)
{
    int idx = blockIdx.x * blockDim.x + threadIdx.x;
    if (idx >= Bq * D) return;
    int q = idx / D;
    int vd = idx - q * D;
    float M = -FLT_MAX;
    #pragma unroll
    for (int s = 0; s < NSPLIT; s++) M = fmaxf(M, g_m[s * MAXB + q]);
    float num = 0.f, den = 0.f;
    #pragma unroll
    for (int s = 0; s < NSPLIT; s++) {
        float wv = __expf(g_m[s * MAXB + q] - M);
        den += wv * g_l[s * MAXB + q];
        num += wv * g_Opart[((size_t)s * MAXB + q) * D + vd];
    }
    out[idx] = num / den;
}

extern "C" void kernel_launch(void* const* d_in, const int* in_sizes, int n_in,
                              void* d_out, int out_size)
{
    const float* q  = (const float*)d_in[0];
    const float* k  = (const float*)d_in[1];
    const float* v  = (const float*)d_in[2];
    const float* Kc = (const float*)d_in[3];
    const float* Vc = (const float*)d_in[4];
    const int* oldp = (const int*)d_in[5];
    int Bq = in_sizes[0] / D;

    cudaFuncSetAttribute((const void*)attn_mma,
                         cudaFuncAttributeMaxDynamicSharedMemorySize, SMEM_BYTES);
    dim3 grid(Bq / BM, NSPLIT);
    attn_mma<<<grid, NTHR, SMEM_BYTES>>>(q, k, v, Kc, Vc, oldp, Bq);
    combine_kernel<<<(Bq * D + 255) / 256, 256>>>((float*)d_out, Bq);
}

// round 8
// speedup vs baseline: 3.7316x; 1.4833x over previous
#include <cuda_runtime.h>
#include <cuda_bf16.h>
#include <math.h>
#include <float.h>

#define D      256
#define BM     32
#define BN     64
#define NSPLIT 4
#define NTHR   256
#define QSTR   264
#define KSTR   72
#define MAXB   2048
#define MAXROWS 34944   // MEMORY_SIZE + B + pad

// ---- smem layout (bytes) ----
#define OFF_QHI 0
#define OFF_QLO 16896
#define OFF_KV  33792              // 2 buffers x (hi 9216 + lo 9216)
#define KVBUF   18432
#define KVLO    9216
#define OFF_PHI 70656
#define OFF_PLO 75264
#define OFF_FLT 79872
#define SMEM_BYTES 81280

__device__ float g_Opart[(size_t)NSPLIT * MAXB * D];
__device__ float g_m[NSPLIT * MAXB];
__device__ float g_l[NSPLIT * MAXB];
__device__ __nv_bfloat16 g_Kh[(size_t)MAXROWS * D];
__device__ __nv_bfloat16 g_Kl[(size_t)MAXROWS * D];
__device__ __nv_bfloat16 g_Vh[(size_t)MAXROWS * D];
__device__ __nv_bfloat16 g_Vl[(size_t)MAXROWS * D];

__device__ __forceinline__ float bfr(float x) {
    return __bfloat162float(__float2bfloat16(x));
}
__device__ __forceinline__ unsigned pack_bf2(float a, float b) {
    __nv_bfloat162 t = __floats2bfloat162_rn(a, b);
    return *reinterpret_cast<unsigned*>(&t);
}
__device__ __forceinline__ void mma_bf16(float* c, unsigned a0, unsigned a1,
                                         unsigned a2, unsigned a3,
                                         unsigned b0, unsigned b1) {
    asm volatile(
        "mma.sync.aligned.m16n8k16.row.col.f32.bf16.bf16.f32 "
        "{%0,%1,%2,%3}, {%4,%5,%6,%7}, {%8,%9}, {%0,%1,%2,%3};\n"
        : "+f"(c[0]), "+f"(c[1]), "+f"(c[2]), "+f"(c[3])
        : "r"(a0), "r"(a1), "r"(a2), "r"(a3), "r"(b0), "r"(b1));
}
__device__ __forceinline__ void ldsm_x4(unsigned& r0, unsigned& r1, unsigned& r2,
                                        unsigned& r3, unsigned a) {
    asm volatile("ldmatrix.sync.aligned.m8n8.x4.shared.b16 {%0,%1,%2,%3}, [%4];"
                 : "=r"(r0), "=r"(r1), "=r"(r2), "=r"(r3) : "r"(a));
}
__device__ __forceinline__ void ldsm_x2(unsigned& r0, unsigned& r1, unsigned a) {
    asm volatile("ldmatrix.sync.aligned.m8n8.x2.shared.b16 {%0,%1}, [%2];"
                 : "=r"(r0), "=r"(r1) : "r"(a));
}
__device__ __forceinline__ void ldsm_x2t(unsigned& r0, unsigned& r1, unsigned a) {
    asm volatile("ldmatrix.sync.aligned.m8n8.x2.trans.shared.b16 {%0,%1}, [%2];"
                 : "=r"(r0), "=r"(r1) : "r"(a));
}
__device__ __forceinline__ void cpa16(unsigned dst, const void* src) {
    asm volatile("cp.async.cg.shared.global [%0], [%1], 16;" :: "r"(dst), "l"(src));
}
__device__ __forceinline__ void cp_commit() {
    asm volatile("cp.async.commit_group;");
}
__device__ __forceinline__ void cp_wait0() {
    asm volatile("cp.async.wait_group 0;");
}

// issue async copy of one 64-key x 64-dim hi/lo chunk into smem buffer
__device__ __forceinline__ void stage_async(const __nv_bfloat16* Gh,
                                            const __nv_bfloat16* Gl,
                                            int kb, int dc, int t, unsigned kvbase) {
    #pragma unroll
    for (int p = 0; p < 2; p++) {
        int g   = t + NTHR * p;          // 0..511
        int row = g >> 3;
        int c8  = (g & 7) * 8;
        size_t soff = (size_t)(kb + row) * D + dc * 64 + c8;
        unsigned doff = (unsigned)((row * KSTR + c8) * 2);
        cpa16(kvbase + doff,         Gh + soff);
        cpa16(kvbase + KVLO + doff,  Gl + soff);
    }
}

// ---- preconvert: fp32 K/V (cache+fresh concat) -> bf16 hi/lo, zero pad ----
extern "C" __global__ void preconvert(const float* __restrict__ Kc,
                                      const float* __restrict__ Vc,
                                      const float* __restrict__ Kn,
                                      const float* __restrict__ Vn,
                                      const int* __restrict__ old_ptr, int Bq)
{
    int old = *old_ptr;
    int nsz = old + Bq;
    int idx = blockIdx.x * blockDim.x + threadIdx.x;   // one per 4 elems
    int row = idx >> 6;
    int c4  = (idx & 63) * 4;
    if (row >= MAXROWS) return;
    size_t o = (size_t)row * D + c4;
    if (row < nsz) {
        const float* ks = (row < old) ? (Kc + (size_t)row * D)
                                      : (Kn + (size_t)(row - old) * D);
        const float* vs = (row < old) ? (Vc + (size_t)row * D)
                                      : (Vn + (size_t)(row - old) * D);
        float4 kv = *(const float4*)(ks + c4);
        float4 vv = *(const float4*)(vs + c4);
        float khx = bfr(kv.x), khy = bfr(kv.y), khz = bfr(kv.z), khw = bfr(kv.w);
        float vhx = bfr(vv.x), vhy = bfr(vv.y), vhz = bfr(vv.z), vhw = bfr(vv.w);
        *(uint2*)&g_Kh[o] = make_uint2(pack_bf2(khx, khy), pack_bf2(khz, khw));
        *(uint2*)&g_Kl[o] = make_uint2(pack_bf2(kv.x - khx, kv.y - khy),
                                       pack_bf2(kv.z - khz, kv.w - khw));
        *(uint2*)&g_Vh[o] = make_uint2(pack_bf2(vhx, vhy), pack_bf2(vhz, vhw));
        *(uint2*)&g_Vl[o] = make_uint2(pack_bf2(vv.x - vhx, vv.y - vhy),
                                       pack_bf2(vv.z - vhz, vv.w - vhw));
    } else if (row < nsz + 64) {
        uint2 z = make_uint2(0u, 0u);
        *(uint2*)&g_Kh[o] = z; *(uint2*)&g_Kl[o] = z;
        *(uint2*)&g_Vh[o] = z; *(uint2*)&g_Vl[o] = z;
    }
}

extern "C" __global__ void __launch_bounds__(NTHR, 2)
attn_mma(const float* __restrict__ Qg, const int* __restrict__ old_ptr, int Bq)
{
    extern __shared__ char smraw[];
    __nv_bfloat16* Qhi = (__nv_bfloat16*)(smraw + OFF_QHI);
    __nv_bfloat16* Qlo = (__nv_bfloat16*)(smraw + OFF_QLO);
    __nv_bfloat16* Phi = (__nv_bfloat16*)(smraw + OFF_PHI);
    __nv_bfloat16* Plo = (__nv_bfloat16*)(smraw + OFF_PLO);
    float* m_s  = (float*)(smraw + OFF_FLT);
    float* l_s  = m_s + 32;
    float* oscs = l_s + 32;
    float* redm = oscs + 32;   // [32][4]
    float* reds = redm + 128;  // [32][4]

    const unsigned smb = (unsigned)__cvta_generic_to_shared(smraw);
    const int t    = threadIdx.x;
    const int lane = t & 31;
    const int w    = t >> 5;
    const int grp  = lane >> 2;
    const int qd   = lane & 3;
    const int mg   = w & 1;
    const int ng   = w >> 1;

    const int old = *old_ptr;
    const int nsz = old + Bq;
    const int q0  = blockIdx.x * BM;
    const int split = blockIdx.y;

    const int kmax  = min(nsz, old + q0 + BM);
    const int chunk = ((kmax + NSPLIT * BN - 1) / (NSPLIT * BN)) * BN;
    const int kbeg  = split * chunk;
    const int kend  = min(kbeg + chunk, kmax);

    // stage Q (pre-scaled 1/16), hi/lo split
    #pragma unroll
    for (int p = 0; p < 8; p++) {
        int idx = t + NTHR * p;
        int r   = idx >> 6;
        int c4  = (idx & 63) * 4;
        float4 v = *(const float4*)(Qg + (size_t)(q0 + r) * D + c4);
        v.x *= 0.0625f; v.y *= 0.0625f; v.z *= 0.0625f; v.w *= 0.0625f;
        float hx = bfr(v.x), hy = bfr(v.y), hz = bfr(v.z), hw = bfr(v.w);
        *(uint2*)&Qhi[r * QSTR + c4] = make_uint2(pack_bf2(hx, hy), pack_bf2(hz, hw));
        *(uint2*)&Qlo[r * QSTR + c4] = make_uint2(pack_bf2(v.x - hx, v.y - hy),
                                                  pack_bf2(v.z - hz, v.w - hw));
    }
    if (t < 32) { m_s[t] = -FLT_MAX; l_s[t] = 0.f; }

    float Of[4][2][4];
    #pragma unroll
    for (int a = 0; a < 4; a++)
        #pragma unroll
        for (int b = 0; b < 2; b++)
            #pragma unroll
            for (int c = 0; c < 4; c++) Of[a][b][c] = 0.f;

    // prologue: prefetch K chunk 0 of first tile into buffer 0
    stage_async(g_Kh, g_Kl, kbeg, 0, t, smb + OFF_KV);
    cp_commit();

    for (int kb = kbeg; kb < kend; kb += BN) {
        float S[2][4];
        #pragma unroll
        for (int nt = 0; nt < 2; nt++)
            #pragma unroll
            for (int i = 0; i < 4; i++) S[nt][i] = 0.f;

        #pragma unroll
        for (int c = 0; c < 8; c++) {
            cp_wait0();
            __syncthreads();
            // prefetch chunk c+1 into buffer (c+1)&1
            {
                unsigned nb = smb + OFF_KV + ((unsigned)((c + 1) & 1)) * KVBUF;
                if (c < 3)       stage_async(g_Kh, g_Kl, kb, c + 1, t, nb);
                else if (c == 3) stage_async(g_Vh, g_Vl, kb, 0, t, nb);
                else if (c < 7)  stage_async(g_Vh, g_Vl, kb, c - 3, t, nb);
                else if (kb + BN < kend)
                                 stage_async(g_Kh, g_Kl, kb + BN, 0, t, nb);
            }
            cp_commit();

            const unsigned kvb = smb + OFF_KV + ((unsigned)(c & 1)) * KVBUF;

            if (c < 4) {
                // ---------- S += Q K^T (chunk dc=c) ----------
                const int dc = c;
                #pragma unroll
                for (int ks = 0; ks < 4; ks++) {
                    int arow = 16 * mg + (lane & 7) + 8 * ((lane >> 3) & 1);
                    int acol = dc * 64 + ks * 16 + 8 * (lane >> 4);
                    unsigned aq = smb + OFF_QHI + (unsigned)(arow * QSTR + acol) * 2u;
                    unsigned ah0, ah1, ah2, ah3, al0, al1, al2, al3;
                    ldsm_x4(ah0, ah1, ah2, ah3, aq);
                    ldsm_x4(al0, al1, al2, al3, aq + (OFF_QLO - OFF_QHI));
                    #pragma unroll
                    for (int nt = 0; nt < 2; nt++) {
                        int bkey = 16 * ng + 8 * nt + (lane & 7);
                        int bcol = ks * 16 + 8 * ((lane >> 3) & 1);
                        unsigned ba = kvb + (unsigned)(bkey * KSTR + bcol) * 2u;
                        unsigned bh0, bh1, bl0, bl1;
                        ldsm_x2(bh0, bh1, ba);
                        ldsm_x2(bl0, bl1, ba + KVLO);
                        mma_bf16(S[nt], ah0, ah1, ah2, ah3, bh0, bh1);
                        mma_bf16(S[nt], ah0, ah1, ah2, ah3, bl0, bl1);
                        mma_bf16(S[nt], al0, al1, al2, al3, bh0, bh1);
                    }
                }
            } else {
                if (c == 4) {
                    // ---------- online softmax ----------
                    const int R0 = 16 * mg + grp, R1 = R0 + 8;
                    const int lim0 = old + q0 + R0, lim1 = old + q0 + R1;
                    float mx0 = -FLT_MAX, mx1 = -FLT_MAX;
                    #pragma unroll
                    for (int nt = 0; nt < 2; nt++) {
                        int kcb = kb + 16 * ng + 8 * nt + 2 * qd;
                        mx0 = fmaxf(mx0, fmaxf((kcb     <= lim0) ? S[nt][0] : -FLT_MAX,
                                               (kcb + 1 <= lim0) ? S[nt][1] : -FLT_MAX));
                        mx1 = fmaxf(mx1, fmaxf((kcb     <= lim1) ? S[nt][2] : -FLT_MAX,
                                               (kcb + 1 <= lim1) ? S[nt][3] : -FLT_MAX));
                    }
                    mx0 = fmaxf(mx0, __shfl_xor_sync(0xffffffffu, mx0, 1));
                    mx0 = fmaxf(mx0, __shfl_xor_sync(0xffffffffu, mx0, 2));
                    mx1 = fmaxf(mx1, __shfl_xor_sync(0xffffffffu, mx1, 1));
                    mx1 = fmaxf(mx1, __shfl_xor_sync(0xffffffffu, mx1, 2));
                    if (qd == 0) { redm[R0 * 4 + ng] = mx0; redm[R1 * 4 + ng] = mx1; }
                    __syncthreads();

                    float mf0 = m_s[R0], mf1 = m_s[R1];
                    #pragma unroll
                    for (int g = 0; g < 4; g++) {
                        mf0 = fmaxf(mf0, redm[R0 * 4 + g]);
                        mf1 = fmaxf(mf1, redm[R1 * 4 + g]);
                    }
                    float sum0 = 0.f, sum1 = 0.f;
                    #pragma unroll
                    for (int nt = 0; nt < 2; nt++) {
                        int kcb = kb + 16 * ng + 8 * nt + 2 * qd;
                        float p0 = (kcb     <= lim0) ? __expf(S[nt][0] - mf0) : 0.f;
                        float p1 = (kcb + 1 <= lim0) ? __expf(S[nt][1] - mf0) : 0.f;
                        float p2 = (kcb     <= lim1) ? __expf(S[nt][2] - mf1) : 0.f;
                        float p3 = (kcb + 1 <= lim1) ? __expf(S[nt][3] - mf1) : 0.f;
                        sum0 += p0 + p1; sum1 += p2 + p3;
                        float h0 = bfr(p0), h1 = bfr(p1), h2 = bfr(p2), h3 = bfr(p3);
                        int kc = 16 * ng + 8 * nt + 2 * qd;
                        *(unsigned*)&Phi[R0 * KSTR + kc] = pack_bf2(h0, h1);
                        *(unsigned*)&Phi[R1 * KSTR + kc] = pack_bf2(h2, h3);
                        *(unsigned*)&Plo[R0 * KSTR + kc] = pack_bf2(p0 - h0, p1 - h1);
                        *(unsigned*)&Plo[R1 * KSTR + kc] = pack_bf2(p2 - h2, p3 - h3);
                    }
                    sum0 += __shfl_xor_sync(0xffffffffu, sum0, 1);
                    sum0 += __shfl_xor_sync(0xffffffffu, sum0, 2);
                    sum1 += __shfl_xor_sync(0xffffffffu, sum1, 1);
                    sum1 += __shfl_xor_sync(0xffffffffu, sum1, 2);
                    if (qd == 0) { reds[R0 * 4 + ng] = sum0; reds[R1 * 4 + ng] = sum1; }
                    __syncthreads();

                    if (t < 32) {
                        float mo = m_s[t], mf = mo;
                        #pragma unroll
                        for (int g = 0; g < 4; g++) mf = fmaxf(mf, redm[t * 4 + g]);
                        float sc = __expf(mo - mf);
                        l_s[t] = l_s[t] * sc + reds[t * 4] + reds[t * 4 + 1]
                                             + reds[t * 4 + 2] + reds[t * 4 + 3];
                        m_s[t] = mf;
                        oscs[t] = sc;
                    }
                    __syncthreads();

                    float s0 = oscs[grp],      s1 = oscs[grp + 8];
                    float s2 = oscs[grp + 16], s3 = oscs[grp + 24];
                    #pragma unroll
                    for (int dcx = 0; dcx < 4; dcx++) {
                        Of[dcx][0][0] *= s0; Of[dcx][0][1] *= s0;
                        Of[dcx][0][2] *= s1; Of[dcx][0][3] *= s1;
                        Of[dcx][1][0] *= s2; Of[dcx][1][1] *= s2;
                        Of[dcx][1][2] *= s3; Of[dcx][1][3] *= s3;
                    }
                }

                // ---------- O += P V (chunk dc=c-4) ----------
                const int dc = c - 4;
                #pragma unroll
                for (int kk = 0; kk < 4; kk++) {
                    int bkey = kk * 16 + (lane & 7) + 8 * ((lane >> 3) & 1);
                    unsigned ba = kvb + (unsigned)(bkey * KSTR + w * 8) * 2u;
                    unsigned bh0, bh1, bl0, bl1;
                    ldsm_x2t(bh0, bh1, ba);
                    ldsm_x2t(bl0, bl1, ba + KVLO);
                    #pragma unroll
                    for (int mt = 0; mt < 2; mt++) {
                        int arow = 16 * mt + (lane & 7) + 8 * ((lane >> 3) & 1);
                        int acol = kk * 16 + 8 * (lane >> 4);
                        unsigned pa = smb + OFF_PHI + (unsigned)(arow * KSTR + acol) * 2u;
                        unsigned ph0, ph1, ph2, ph3, pl0, pl1, pl2, pl3;
                        ldsm_x4(ph0, ph1, ph2, ph3, pa);
                        ldsm_x4(pl0, pl1, pl2, pl3, pa + (OFF_PLO - OFF_PHI));
                        mma_bf16(Of[dc][mt], ph0, ph1, ph2, ph3, bh0, bh1);
                        mma_bf16(Of[dc][mt], ph0, ph1, ph2, ph3, bl0, bl1);
                        mma_bf16(Of[dc][mt], pl0, pl1, pl2, pl3, bh0, bh1);
                    }
                }
            }
        }
    }

    __syncthreads();
    size_t obase = ((size_t)split * MAXB + q0) * D;
    #pragma unroll
    for (int dc = 0; dc < 4; dc++) {
        int d = dc * 64 + w * 8 + 2 * qd;
        #pragma unroll
        for (int mt = 0; mt < 2; mt++) {
            int r = 16 * mt + grp;
            *(float2*)&g_Opart[obase + (size_t)r * D + d] =
                make_float2(Of[dc][mt][0], Of[dc][mt][1]);
            *(float2*)&g_Opart[obase + (size_t)(r + 8) * D + d] =
                make_float2(Of[dc][mt][2], Of[dc][mt][3]);
        }
    }
    if (t < 32) {
        g_m[split * MAXB + q0 + t] = m_s[t];
        g_l[split * MAXB + q0 + t] = l_s[t];
    }
}

extern "C" __global__ void combine_kernel(float* __restrict__ out, int Bq)
{
    int idx = blockIdx.x * blockDim.x + threadIdx.x;
    if (idx >= Bq * D) return;
    int q = idx / D;
    int vd = idx - q * D;
    float M = -FLT_MAX;
    #pragma unroll
    for (int s = 0; s < NSPLIT; s++) M = fmaxf(M, g_m[s * MAXB + q]);
    float num = 0.f, den = 0.f;
    #pragma unroll
    for (int s = 0; s < NSPLIT; s++) {
        float wv = __expf(g_m[s * MAXB + q] - M);
        den += wv * g_l[s * MAXB + q];
        num += wv * g_Opart[((size_t)s * MAXB + q) * D + vd];
    }
    out[idx] = num / den;
}

extern "C" void kernel_launch(void* const* d_in, const int* in_sizes, int n_in,
                              void* d_out, int out_size)
{
    const float* q  = (const float*)d_in[0];
    const float* k  = (const float*)d_in[1];
    const float* v  = (const float*)d_in[2];
    const float* Kc = (const float*)d_in[3];
    const float* Vc = (const float*)d_in[4];
    const int* oldp = (const int*)d_in[5];
    int Bq      = in_sizes[0] / D;
    int memrows = in_sizes[3] / D;

    // preconvert K/V to bf16 hi/lo (covers up to memrows + Bq + pad rows)
    int rows = memrows + Bq + 64;
    if (rows > MAXROWS) rows = MAXROWS;
    long total = (long)rows * 64;   // one thread per 4 elements
    preconvert<<<(unsigned)((total + 255) / 256), 256>>>(Kc, Vc, k, v, oldp, Bq);

    cudaFuncSetAttribute((const void*)attn_mma,
                         cudaFuncAttributeMaxDynamicSharedMemorySize, SMEM_BYTES);
    dim3 grid(Bq / BM, NSPLIT);
    attn_mma<<<grid, NTHR, SMEM_BYTES>>>(q, oldp, Bq);
    combine_kernel<<<(Bq * D + 255) / 256, 256>>>((float*)d_out, Bq);
}

// round 9
// speedup vs baseline: 3.7478x; 1.0044x over previous
#include <cuda_runtime.h>
#include <cuda_bf16.h>
#include <math.h>
#include <float.h>

#define D      256
#define BM     32
#define BN     64
#define NSPLIT 4
#define NTHR   256
#define QSTR   264
#define KSTR   72
#define MAXB   2048
#define MAXROWS 34944   // MEMORY_SIZE + B + pad

// ---- smem layout (bytes) ----
#define OFF_QHI 0
#define OFF_QLO 16896
#define OFF_KV  33792              // 2 buffers x (hi 9216 + lo 9216)
#define KVBUF   18432
#define KVLO    9216
#define OFF_PHI 70656
#define OFF_PLO 75264
#define OFF_FLT 79872
#define SMEM_BYTES 81280

__device__ float g_Opart[(size_t)NSPLIT * MAXB * D];
__device__ float g_m[NSPLIT * MAXB];
__device__ float g_l[NSPLIT * MAXB];
__device__ __nv_bfloat16 g_Kh[(size_t)MAXROWS * D];
__device__ __nv_bfloat16 g_Kl[(size_t)MAXROWS * D];
__device__ __nv_bfloat16 g_Vh[(size_t)MAXROWS * D];
__device__ __nv_bfloat16 g_Vl[(size_t)MAXROWS * D];

__device__ __forceinline__ float bfr(float x) {
    return __bfloat162float(__float2bfloat16(x));
}
__device__ __forceinline__ unsigned pack_bf2(float a, float b) {
    __nv_bfloat162 t = __floats2bfloat162_rn(a, b);
    return *reinterpret_cast<unsigned*>(&t);
}
__device__ __forceinline__ void mma_bf16(float* c, unsigned a0, unsigned a1,
                                         unsigned a2, unsigned a3,
                                         unsigned b0, unsigned b1) {
    asm volatile(
        "mma.sync.aligned.m16n8k16.row.col.f32.bf16.bf16.f32 "
        "{%0,%1,%2,%3}, {%4,%5,%6,%7}, {%8,%9}, {%0,%1,%2,%3};\n"
        : "+f"(c[0]), "+f"(c[1]), "+f"(c[2]), "+f"(c[3])
        : "r"(a0), "r"(a1), "r"(a2), "r"(a3), "r"(b0), "r"(b1));
}
__device__ __forceinline__ void ldsm_x4(unsigned& r0, unsigned& r1, unsigned& r2,
                                        unsigned& r3, unsigned a) {
    asm volatile("ldmatrix.sync.aligned.m8n8.x4.shared.b16 {%0,%1,%2,%3}, [%4];"
                 : "=r"(r0), "=r"(r1), "=r"(r2), "=r"(r3) : "r"(a));
}
__device__ __forceinline__ void ldsm_x2(unsigned& r0, unsigned& r1, unsigned a) {
    asm volatile("ldmatrix.sync.aligned.m8n8.x2.shared.b16 {%0,%1}, [%2];"
                 : "=r"(r0), "=r"(r1) : "r"(a));
}
__device__ __forceinline__ void ldsm_x2t(unsigned& r0, unsigned& r1, unsigned a) {
    asm volatile("ldmatrix.sync.aligned.m8n8.x2.trans.shared.b16 {%0,%1}, [%2];"
                 : "=r"(r0), "=r"(r1) : "r"(a));
}
__device__ __forceinline__ void cpa16(unsigned dst, const void* src) {
    asm volatile("cp.async.cg.shared.global [%0], [%1], 16;" :: "r"(dst), "l"(src));
}
__device__ __forceinline__ void cp_commit() {
    asm volatile("cp.async.commit_group;");
}
__device__ __forceinline__ void cp_wait0() {
    asm volatile("cp.async.wait_group 0;");
}

// issue async copy of one 64-key x 64-dim hi/lo chunk into smem buffer
__device__ __forceinline__ void stage_async(const __nv_bfloat16* Gh,
                                            const __nv_bfloat16* Gl,
                                            int kb, int dc, int t, unsigned kvbase) {
    #pragma unroll
    for (int p = 0; p < 2; p++) {
        int g   = t + NTHR * p;          // 0..511
        int row = g >> 3;
        int c8  = (g & 7) * 8;
        size_t soff = (size_t)(kb + row) * D + dc * 64 + c8;
        unsigned doff = (unsigned)((row * KSTR + c8) * 2);
        cpa16(kvbase + doff,         Gh + soff);
        cpa16(kvbase + KVLO + doff,  Gl + soff);
    }
}

// ---- preconvert: fp32 K/V (cache+fresh concat) -> bf16 hi/lo, zero pad ----
extern "C" __global__ void preconvert(const float* __restrict__ Kc,
                                      const float* __restrict__ Vc,
                                      const float* __restrict__ Kn,
                                      const float* __restrict__ Vn,
                                      const int* __restrict__ old_ptr, int Bq)
{
    int old = *old_ptr;
    int nsz = old + Bq;
    int idx = blockIdx.x * blockDim.x + threadIdx.x;   // one per 4 elems
    int row = idx >> 6;
    int c4  = (idx & 63) * 4;
    if (row >= MAXROWS) return;
    size_t o = (size_t)row * D + c4;
    if (row < nsz) {
        const float* ks = (row < old) ? (Kc + (size_t)row * D)
                                      : (Kn + (size_t)(row - old) * D);
        const float* vs = (row < old) ? (Vc + (size_t)row * D)
                                      : (Vn + (size_t)(row - old) * D);
        float4 kv = *(const float4*)(ks + c4);
        float4 vv = *(const float4*)(vs + c4);
        float khx = bfr(kv.x), khy = bfr(kv.y), khz = bfr(kv.z), khw = bfr(kv.w);
        float vhx = bfr(vv.x), vhy = bfr(vv.y), vhz = bfr(vv.z), vhw = bfr(vv.w);
        *(uint2*)&g_Kh[o] = make_uint2(pack_bf2(khx, khy), pack_bf2(khz, khw));
        *(uint2*)&g_Kl[o] = make_uint2(pack_bf2(kv.x - khx, kv.y - khy),
                                       pack_bf2(kv.z - khz, kv.w - khw));
        *(uint2*)&g_Vh[o] = make_uint2(pack_bf2(vhx, vhy), pack_bf2(vhz, vhw));
        *(uint2*)&g_Vl[o] = make_uint2(pack_bf2(vv.x - vhx, vv.y - vhy),
                                       pack_bf2(vv.z - vhz, vv.w - vhw));
    } else if (row < nsz + 64) {
        uint2 z = make_uint2(0u, 0u);
        *(uint2*)&g_Kh[o] = z; *(uint2*)&g_Kl[o] = z;
        *(uint2*)&g_Vh[o] = z; *(uint2*)&g_Vl[o] = z;
    }
}

extern "C" __global__ void __launch_bounds__(NTHR, 2)
attn_mma(const float* __restrict__ Qg, const int* __restrict__ old_ptr, int Bq)
{
    extern __shared__ char smraw[];
    __nv_bfloat16* Qhi = (__nv_bfloat16*)(smraw + OFF_QHI);
    __nv_bfloat16* Qlo = (__nv_bfloat16*)(smraw + OFF_QLO);
    __nv_bfloat16* Phi = (__nv_bfloat16*)(smraw + OFF_PHI);
    __nv_bfloat16* Plo = (__nv_bfloat16*)(smraw + OFF_PLO);
    float* m_s  = (float*)(smraw + OFF_FLT);
    float* l_s  = m_s + 32;
    float* oscs = l_s + 32;
    float* redm = oscs + 32;   // [32][4]
    float* reds = redm + 128;  // [32][4]

    const unsigned smb = (unsigned)__cvta_generic_to_shared(smraw);
    const int t    = threadIdx.x;
    const int lane = t & 31;
    const int w    = t >> 5;
    const int grp  = lane >> 2;
    const int qd   = lane & 3;
    const int mg   = w & 1;
    const int ng   = w >> 1;

    const int old = *old_ptr;
    const int nsz = old + Bq;
    const int q0  = blockIdx.x * BM;
    const int split = blockIdx.y;

    const int kmax  = min(nsz, old + q0 + BM);
    const int chunk = ((kmax + NSPLIT * BN - 1) / (NSPLIT * BN)) * BN;
    const int kbeg  = split * chunk;
    const int kend  = min(kbeg + chunk, kmax);

    // stage Q (pre-scaled 1/16), hi/lo split
    #pragma unroll
    for (int p = 0; p < 8; p++) {
        int idx = t + NTHR * p;
        int r   = idx >> 6;
        int c4  = (idx & 63) * 4;
        float4 v = *(const float4*)(Qg + (size_t)(q0 + r) * D + c4);
        v.x *= 0.0625f; v.y *= 0.0625f; v.z *= 0.0625f; v.w *= 0.0625f;
        float hx = bfr(v.x), hy = bfr(v.y), hz = bfr(v.z), hw = bfr(v.w);
        *(uint2*)&Qhi[r * QSTR + c4] = make_uint2(pack_bf2(hx, hy), pack_bf2(hz, hw));
        *(uint2*)&Qlo[r * QSTR + c4] = make_uint2(pack_bf2(v.x - hx, v.y - hy),
                                                  pack_bf2(v.z - hz, v.w - hw));
    }
    if (t < 32) { m_s[t] = -FLT_MAX; l_s[t] = 0.f; }

    float Of[4][2][4];
    #pragma unroll
    for (int a = 0; a < 4; a++)
        #pragma unroll
        for (int b = 0; b < 2; b++)
            #pragma unroll
            for (int c = 0; c < 4; c++) Of[a][b][c] = 0.f;

    // prologue: prefetch K chunk 0 of first tile into buffer 0
    stage_async(g_Kh, g_Kl, kbeg, 0, t, smb + OFF_KV);
    cp_commit();

    for (int kb = kbeg; kb < kend; kb += BN) {
        float S[2][4];
        #pragma unroll
        for (int nt = 0; nt < 2; nt++)
            #pragma unroll
            for (int i = 0; i < 4; i++) S[nt][i] = 0.f;

        #pragma unroll
        for (int c = 0; c < 8; c++) {
            cp_wait0();
            __syncthreads();
            // prefetch chunk c+1 into buffer (c+1)&1
            {
                unsigned nb = smb + OFF_KV + ((unsigned)((c + 1) & 1)) * KVBUF;
                if (c < 3)       stage_async(g_Kh, g_Kl, kb, c + 1, t, nb);
                else if (c == 3) stage_async(g_Vh, g_Vl, kb, 0, t, nb);
                else if (c < 7)  stage_async(g_Vh, g_Vl, kb, c - 3, t, nb);
                else if (kb + BN < kend)
                                 stage_async(g_Kh, g_Kl, kb + BN, 0, t, nb);
            }
            cp_commit();

            const unsigned kvb = smb + OFF_KV + ((unsigned)(c & 1)) * KVBUF;

            if (c < 4) {
                // ---------- S += Q K^T (chunk dc=c) ----------
                const int dc = c;
                #pragma unroll
                for (int ks = 0; ks < 4; ks++) {
                    int arow = 16 * mg + (lane & 7) + 8 * ((lane >> 3) & 1);
                    int acol = dc * 64 + ks * 16 + 8 * (lane >> 4);
                    unsigned aq = smb + OFF_QHI + (unsigned)(arow * QSTR + acol) * 2u;
                    unsigned ah0, ah1, ah2, ah3, al0, al1, al2, al3;
                    ldsm_x4(ah0, ah1, ah2, ah3, aq);
                    ldsm_x4(al0, al1, al2, al3, aq + (OFF_QLO - OFF_QHI));
                    #pragma unroll
                    for (int nt = 0; nt < 2; nt++) {
                        int bkey = 16 * ng + 8 * nt + (lane & 7);
                        int bcol = ks * 16 + 8 * ((lane >> 3) & 1);
                        unsigned ba = kvb + (unsigned)(bkey * KSTR + bcol) * 2u;
                        unsigned bh0, bh1, bl0, bl1;
                        ldsm_x2(bh0, bh1, ba);
                        ldsm_x2(bl0, bl1, ba + KVLO);
                        mma_bf16(S[nt], ah0, ah1, ah2, ah3, bh0, bh1);
                        mma_bf16(S[nt], ah0, ah1, ah2, ah3, bl0, bl1);
                        mma_bf16(S[nt], al0, al1, al2, al3, bh0, bh1);
                    }
                }
            } else {
                if (c == 4) {
                    // ---------- online softmax ----------
                    const int R0 = 16 * mg + grp, R1 = R0 + 8;
                    const int lim0 = old + q0 + R0, lim1 = old + q0 + R1;
                    float mx0 = -FLT_MAX, mx1 = -FLT_MAX;
                    #pragma unroll
                    for (int nt = 0; nt < 2; nt++) {
                        int kcb = kb + 16 * ng + 8 * nt + 2 * qd;
                        mx0 = fmaxf(mx0, fmaxf((kcb     <= lim0) ? S[nt][0] : -FLT_MAX,
                                               (kcb + 1 <= lim0) ? S[nt][1] : -FLT_MAX));
                        mx1 = fmaxf(mx1, fmaxf((kcb     <= lim1) ? S[nt][2] : -FLT_MAX,
                                               (kcb + 1 <= lim1) ? S[nt][3] : -FLT_MAX));
                    }
                    mx0 = fmaxf(mx0, __shfl_xor_sync(0xffffffffu, mx0, 1));
                    mx0 = fmaxf(mx0, __shfl_xor_sync(0xffffffffu, mx0, 2));
                    mx1 = fmaxf(mx1, __shfl_xor_sync(0xffffffffu, mx1, 1));
                    mx1 = fmaxf(mx1, __shfl_xor_sync(0xffffffffu, mx1, 2));
                    if (qd == 0) { redm[R0 * 4 + ng] = mx0; redm[R1 * 4 + ng] = mx1; }
                    __syncthreads();

                    float mf0 = m_s[R0], mf1 = m_s[R1];
                    #pragma unroll
                    for (int g = 0; g < 4; g++) {
                        mf0 = fmaxf(mf0, redm[R0 * 4 + g]);
                        mf1 = fmaxf(mf1, redm[R1 * 4 + g]);
                    }
                    float sum0 = 0.f, sum1 = 0.f;
                    #pragma unroll
                    for (int nt = 0; nt < 2; nt++) {
                        int kcb = kb + 16 * ng + 8 * nt + 2 * qd;
                        float p0 = (kcb     <= lim0) ? __expf(S[nt][0] - mf0) : 0.f;
                        float p1 = (kcb + 1 <= lim0) ? __expf(S[nt][1] - mf0) : 0.f;
                        float p2 = (kcb     <= lim1) ? __expf(S[nt][2] - mf1) : 0.f;
                        float p3 = (kcb + 1 <= lim1) ? __expf(S[nt][3] - mf1) : 0.f;
                        sum0 += p0 + p1; sum1 += p2 + p3;
                        float h0 = bfr(p0), h1 = bfr(p1), h2 = bfr(p2), h3 = bfr(p3);
                        int kc = 16 * ng + 8 * nt + 2 * qd;
                        *(unsigned*)&Phi[R0 * KSTR + kc] = pack_bf2(h0, h1);
                        *(unsigned*)&Phi[R1 * KSTR + kc] = pack_bf2(h2, h3);
                        *(unsigned*)&Plo[R0 * KSTR + kc] = pack_bf2(p0 - h0, p1 - h1);
                        *(unsigned*)&Plo[R1 * KSTR + kc] = pack_bf2(p2 - h2, p3 - h3);
                    }
                    sum0 += __shfl_xor_sync(0xffffffffu, sum0, 1);
                    sum0 += __shfl_xor_sync(0xffffffffu, sum0, 2);
                    sum1 += __shfl_xor_sync(0xffffffffu, sum1, 1);
                    sum1 += __shfl_xor_sync(0xffffffffu, sum1, 2);
                    if (qd == 0) { reds[R0 * 4 + ng] = sum0; reds[R1 * 4 + ng] = sum1; }
                    __syncthreads();

                    if (t < 32) {
                        float mo = m_s[t], mf = mo;
                        #pragma unroll
                        for (int g = 0; g < 4; g++) mf = fmaxf(mf, redm[t * 4 + g]);
                        float sc = __expf(mo - mf);
                        l_s[t] = l_s[t] * sc + reds[t * 4] + reds[t * 4 + 1]
                                             + reds[t * 4 + 2] + reds[t * 4 + 3];
                        m_s[t] = mf;
                        oscs[t] = sc;
                    }
                    __syncthreads();

                    float s0 = oscs[grp],      s1 = oscs[grp + 8];
                    float s2 = oscs[grp + 16], s3 = oscs[grp + 24];
                    #pragma unroll
                    for (int dcx = 0; dcx < 4; dcx++) {
                        Of[dcx][0][0] *= s0; Of[dcx][0][1] *= s0;
                        Of[dcx][0][2] *= s1; Of[dcx][0][3] *= s1;
                        Of[dcx][1][0] *= s2; Of[dcx][1][1] *= s2;
                        Of[dcx][1][2] *= s3; Of[dcx][1][3] *= s3;
                    }
                }

                // ---------- O += P V (chunk dc=c-4) ----------
                const int dc = c - 4;
                #pragma unroll
                for (int kk = 0; kk < 4; kk++) {
                    int bkey = kk * 16 + (lane & 7) + 8 * ((lane >> 3) & 1);
                    unsigned ba = kvb + (unsigned)(bkey * KSTR + w * 8) * 2u;
                    unsigned bh0, bh1, bl0, bl1;
                    ldsm_x2t(bh0, bh1, ba);
                    ldsm_x2t(bl0, bl1, ba + KVLO);
                    #pragma unroll
                    for (int mt = 0; mt < 2; mt++) {
                        int arow = 16 * mt + (lane & 7) + 8 * ((lane >> 3) & 1);
                        int acol = kk * 16 + 8 * (lane >> 4);
                        unsigned pa = smb + OFF_PHI + (unsigned)(arow * KSTR + acol) * 2u;
                        unsigned ph0, ph1, ph2, ph3, pl0, pl1, pl2, pl3;
                        ldsm_x4(ph0, ph1, ph2, ph3, pa);
                        ldsm_x4(pl0, pl1, pl2, pl3, pa + (OFF_PLO - OFF_PHI));
                        mma_bf16(Of[dc][mt], ph0, ph1, ph2, ph3, bh0, bh1);
                        mma_bf16(Of[dc][mt], ph0, ph1, ph2, ph3, bl0, bl1);
                        mma_bf16(Of[dc][mt], pl0, pl1, pl2, pl3, bh0, bh1);
                    }
                }
            }
        }
    }

    __syncthreads();
    size_t obase = ((size_t)split * MAXB + q0) * D;
    #pragma unroll
    for (int dc = 0; dc < 4; dc++) {
        int d = dc * 64 + w * 8 + 2 * qd;
        #pragma unroll
        for (int mt = 0; mt < 2; mt++) {
            int r = 16 * mt + grp;
            *(float2*)&g_Opart[obase + (size_t)r * D + d] =
                make_float2(Of[dc][mt][0], Of[dc][mt][1]);
            *(float2*)&g_Opart[obase + (size_t)(r + 8) * D + d] =
                make_float2(Of[dc][mt][2], Of[dc][mt][3]);
        }
    }
    if (t < 32) {
        g_m[split * MAXB + q0 + t] = m_s[t];
        g_l[split * MAXB + q0 + t] = l_s[t];
    }
}

extern "C" __global__ void combine_kernel(float* __restrict__ out, int Bq)
{
    int idx = blockIdx.x * blockDim.x + threadIdx.x;
    if (idx >= Bq * D) return;
    int q = idx / D;
    int vd = idx - q * D;
    float M = -FLT_MAX;
    #pragma unroll
    for (int s = 0; s < NSPLIT; s++) M = fmaxf(M, g_m[s * MAXB + q]);
    float num = 0.f, den = 0.f;
    #pragma unroll
    for (int s = 0; s < NSPLIT; s++) {
        float wv = __expf(g_m[s * MAXB + q] - M);
        den += wv * g_l[s * MAXB + q];
        num += wv * g_Opart[((size_t)s * MAXB + q) * D + vd];
    }
    out[idx] = num / den;
}

extern "C" void kernel_launch(void* const* d_in, const int* in_sizes, int n_in,
                              void* d_out, int out_size)
{
    const float* q  = (const float*)d_in[0];
    const float* k  = (const float*)d_in[1];
    const float* v  = (const float*)d_in[2];
    const float* Kc = (const float*)d_in[3];
    const float* Vc = (const float*)d_in[4];
    const int* oldp = (const int*)d_in[5];
    int Bq      = in_sizes[0] / D;
    int memrows = in_sizes[3] / D;

    // preconvert K/V to bf16 hi/lo (covers up to memrows + Bq + pad rows)
    int rows = memrows + Bq + 64;
    if (rows > MAXROWS) rows = MAXROWS;
    long total = (long)rows * 64;   // one thread per 4 elements
    preconvert<<<(unsigned)((total + 255) / 256), 256>>>(Kc, Vc, k, v, oldp, Bq);

    cudaFuncSetAttribute((const void*)attn_mma,
                         cudaFuncAttributeMaxDynamicSharedMemorySize, SMEM_BYTES);
    dim3 grid(Bq / BM, NSPLIT);
    attn_mma<<<grid, NTHR, SMEM_BYTES>>>(q, oldp, Bq);
    combine_kernel<<<(Bq * D + 255) / 256, 256>>>((float*)d_out, Bq);
}

// round 12
// speedup vs baseline: 6.4788x; 1.7287x over previous
#include <cuda_runtime.h>
#include <cuda_fp16.h>
#include <math.h>
#include <float.h>

#define D      256
#define BM     32
#define BN     64
#define NSPLIT 4
#define NTHR   256
#define QSTR   264
#define KSTR   72
#define MAXB   2048
#define MAXROWS 34944

// ---- smem layout (bytes) ----
#define OFF_Q   0                  // 32 x 264 fp16 = 16896
#define OFF_KV  16896              // 2 slots x 9216
#define KVBUF   9216
#define OFF_P   35328              // 32 x 72 fp16 = 4608
#define OFF_FLT 39936
#define SMEM_BYTES 41344

__device__ float g_Opart[(size_t)NSPLIT * MAXB * D];
__device__ float g_m[NSPLIT * MAXB];
__device__ float g_l[NSPLIT * MAXB];
__device__ __half g_K[(size_t)MAXROWS * D];
__device__ __half g_V[(size_t)MAXROWS * D];

__device__ __forceinline__ unsigned pack_h2(float a, float b) {
    __half2 t = __floats2half2_rn(a, b);
    return *reinterpret_cast<unsigned*>(&t);
}
__device__ __forceinline__ void mma_f16(float* c, unsigned a0, unsigned a1,
                                        unsigned a2, unsigned a3,
                                        unsigned b0, unsigned b1) {
    asm volatile(
        "mma.sync.aligned.m16n8k16.row.col.f32.f16.f16.f32 "
        "{%0,%1,%2,%3}, {%4,%5,%6,%7}, {%8,%9}, {%0,%1,%2,%3};\n"
        : "+f"(c[0]), "+f"(c[1]), "+f"(c[2]), "+f"(c[3])
        : "r"(a0), "r"(a1), "r"(a2), "r"(a3), "r"(b0), "r"(b1));
}
__device__ __forceinline__ void ldsm_x4(unsigned& r0, unsigned& r1, unsigned& r2,
                                        unsigned& r3, unsigned a) {
    asm volatile("ldmatrix.sync.aligned.m8n8.x4.shared.b16 {%0,%1,%2,%3}, [%4];"
                 : "=r"(r0), "=r"(r1), "=r"(r2), "=r"(r3) : "r"(a));
}
__device__ __forceinline__ void ldsm_x2(unsigned& r0, unsigned& r1, unsigned a) {
    asm volatile("ldmatrix.sync.aligned.m8n8.x2.shared.b16 {%0,%1}, [%2];"
                 : "=r"(r0), "=r"(r1) : "r"(a));
}
__device__ __forceinline__ void ldsm_x2t(unsigned& r0, unsigned& r1, unsigned a) {
    asm volatile("ldmatrix.sync.aligned.m8n8.x2.trans.shared.b16 {%0,%1}, [%2];"
                 : "=r"(r0), "=r"(r1) : "r"(a));
}
__device__ __forceinline__ void cpa16(unsigned dst, const void* src) {
    asm volatile("cp.async.cg.shared.global [%0], [%1], 16;" :: "r"(dst), "l"(src));
}
#define CP_COMMIT() asm volatile("cp.async.commit_group;")
#define CP_WAIT0()  asm volatile("cp.async.wait_group 0;")

// async copy of one 64-key x 64-dim fp16 chunk into a slot
__device__ __forceinline__ void stage_async(const __half* G, int kb, int dc,
                                            int t, unsigned base) {
    #pragma unroll
    for (int p = 0; p < 2; p++) {
        int g   = t + NTHR * p;          // 0..511
        int row = g >> 3;
        int c8  = (g & 7) * 8;
        cpa16(base + (unsigned)((row * KSTR + c8) * 2),
              G + (size_t)(kb + row) * D + dc * 64 + c8);
    }
}

// ---- preconvert: fp32 K/V (cache+fresh concat) -> fp16, zero pad ----
extern "C" __global__ void preconvert(const float* __restrict__ Kc,
                                      const float* __restrict__ Vc,
                                      const float* __restrict__ Kn,
                                      const float* __restrict__ Vn,
                                      const int* __restrict__ old_ptr, int Bq)
{
    int old = *old_ptr;
    int nsz = old + Bq;
    int idx = blockIdx.x * blockDim.x + threadIdx.x;   // one per 4 elems
    int row = idx >> 6;
    int c4  = (idx & 63) * 4;
    if (row >= MAXROWS) return;
    size_t o = (size_t)row * D + c4;
    if (row < nsz) {
        const float* ks = (row < old) ? (Kc + (size_t)row * D)
                                      : (Kn + (size_t)(row - old) * D);
        const float* vs = (row < old) ? (Vc + (size_t)row * D)
                                      : (Vn + (size_t)(row - old) * D);
        float4 kv = *(const float4*)(ks + c4);
        float4 vv = *(const float4*)(vs + c4);
        *(uint2*)&g_K[o] = make_uint2(pack_h2(kv.x, kv.y), pack_h2(kv.z, kv.w));
        *(uint2*)&g_V[o] = make_uint2(pack_h2(vv.x, vv.y), pack_h2(vv.z, vv.w));
    } else if (row < nsz + 64) {
        uint2 z = make_uint2(0u, 0u);
        *(uint2*)&g_K[o] = z; *(uint2*)&g_V[o] = z;
    }
}

extern "C" __global__ void __launch_bounds__(NTHR, 3)
attn_mma(const float* __restrict__ Qg, const int* __restrict__ old_ptr, int Bq)
{
    extern __shared__ char smraw[];
    __half* Qs = (__half*)(smraw + OFF_Q);
    __half* Ps = (__half*)(smraw + OFF_P);
    float* m_s  = (float*)(smraw + OFF_FLT);
    float* l_s  = m_s + 32;
    float* oscs = l_s + 32;
    float* redm = oscs + 32;   // [32][4]
    float* reds = redm + 128;  // [32][4]

    const unsigned smb = (unsigned)__cvta_generic_to_shared(smraw);
    const int t    = threadIdx.x;
    const int lane = t & 31;
    const int w    = t >> 5;
    const int grp  = lane >> 2;
    const int qd   = lane & 3;
    const int mg   = w & 1;
    const int ng   = w >> 1;

    const int old = *old_ptr;
    const int nsz = old + Bq;
    const int q0  = blockIdx.x * BM;
    const int split = blockIdx.y;

    const int kmax  = min(nsz, old + q0 + BM);
    const int chunk = ((kmax + NSPLIT * BN - 1) / (NSPLIT * BN)) * BN;
    const int kbeg  = split * chunk;
    const int kend  = min(kbeg + chunk, kmax);

    // stage Q (pre-scaled 1/16) as fp16
    #pragma unroll
    for (int p = 0; p < 8; p++) {
        int idx = t + NTHR * p;
        int r   = idx >> 6;
        int c4  = (idx & 63) * 4;
        float4 v = *(const float4*)(Qg + (size_t)(q0 + r) * D + c4);
        *(uint2*)&Qs[r * QSTR + c4] =
            make_uint2(pack_h2(v.x * 0.0625f, v.y * 0.0625f),
                       pack_h2(v.z * 0.0625f, v.w * 0.0625f));
    }
    if (t < 32) { m_s[t] = -FLT_MAX; l_s[t] = 0.f; }

    float Of[4][2][4];
    #pragma unroll
    for (int a = 0; a < 4; a++)
        #pragma unroll
        for (int b = 0; b < 2; b++)
            #pragma unroll
            for (int c = 0; c < 4; c++) Of[a][b][c] = 0.f;

    stage_async(g_K, kbeg, 0, t, smb + OFF_KV);
    CP_COMMIT();

    for (int kb = kbeg; kb < kend; kb += BN) {
        float S[2][4];
        #pragma unroll
        for (int nt = 0; nt < 2; nt++)
            #pragma unroll
            for (int i = 0; i < 4; i++) S[nt][i] = 0.f;

        #pragma unroll
        for (int c = 0; c < 8; c++) {
            CP_WAIT0();
            __syncthreads();
            {
                unsigned nb = smb + OFF_KV + ((unsigned)((c + 1) & 1)) * KVBUF;
                if (c < 3)       stage_async(g_K, kb, c + 1, t, nb);
                else if (c == 3) stage_async(g_V, kb, 0, t, nb);
                else if (c < 7)  stage_async(g_V, kb, c - 3, t, nb);
                else if (kb + BN < kend)
                                 stage_async(g_K, kb + BN, 0, t, nb);
            }
            CP_COMMIT();

            const unsigned kvb = smb + OFF_KV + ((unsigned)(c & 1)) * KVBUF;

            if (c < 4) {
                // ---------- S += Q K^T (dim chunk c) ----------
                const int dc = c;
                #pragma unroll
                for (int ks = 0; ks < 4; ks++) {
                    int arow = 16 * mg + (lane & 7) + 8 * ((lane >> 3) & 1);
                    int acol = dc * 64 + ks * 16 + 8 * (lane >> 4);
                    unsigned aq = smb + OFF_Q + (unsigned)(arow * QSTR + acol) * 2u;
                    unsigned a0, a1, a2, a3;
                    ldsm_x4(a0, a1, a2, a3, aq);
                    #pragma unroll
                    for (int nt = 0; nt < 2; nt++) {
                        int bkey = 16 * ng + 8 * nt + (lane & 7);
                        int bcol = ks * 16 + 8 * ((lane >> 3) & 1);
                        unsigned ba = kvb + (unsigned)(bkey * KSTR + bcol) * 2u;
                        unsigned b0, b1;
                        ldsm_x2(b0, b1, ba);
                        mma_f16(S[nt], a0, a1, a2, a3, b0, b1);
                    }
                }
            } else {
                if (c == 4) {
                    // ---------- online softmax ----------
                    const int R0 = 16 * mg + grp, R1 = R0 + 8;
                    const int lim0 = old + q0 + R0, lim1 = old + q0 + R1;
                    float mx0 = -FLT_MAX, mx1 = -FLT_MAX;
                    #pragma unroll
                    for (int nt = 0; nt < 2; nt++) {
                        int kcb = kb + 16 * ng + 8 * nt + 2 * qd;
                        mx0 = fmaxf(mx0, fmaxf((kcb     <= lim0) ? S[nt][0] : -FLT_MAX,
                                               (kcb + 1 <= lim0) ? S[nt][1] : -FLT_MAX));
                        mx1 = fmaxf(mx1, fmaxf((kcb     <= lim1) ? S[nt][2] : -FLT_MAX,
                                               (kcb + 1 <= lim1) ? S[nt][3] : -FLT_MAX));
                    }
                    mx0 = fmaxf(mx0, __shfl_xor_sync(0xffffffffu, mx0, 1));
                    mx0 = fmaxf(mx0, __shfl_xor_sync(0xffffffffu, mx0, 2));
                    mx1 = fmaxf(mx1, __shfl_xor_sync(0xffffffffu, mx1, 1));
                    mx1 = fmaxf(mx1, __shfl_xor_sync(0xffffffffu, mx1, 2));
                    if (qd == 0) { redm[R0 * 4 + ng] = mx0; redm[R1 * 4 + ng] = mx1; }
                    __syncthreads();

                    float mf0 = m_s[R0], mf1 = m_s[R1];
                    #pragma unroll
                    for (int g = 0; g < 4; g++) {
                        mf0 = fmaxf(mf0, redm[R0 * 4 + g]);
                        mf1 = fmaxf(mf1, redm[R1 * 4 + g]);
                    }
                    float sum0 = 0.f, sum1 = 0.f;
                    #pragma unroll
                    for (int nt = 0; nt < 2; nt++) {
                        int kcb = kb + 16 * ng + 8 * nt + 2 * qd;
                        float p0 = (kcb     <= lim0) ? __expf(S[nt][0] - mf0) : 0.f;
                        float p1 = (kcb + 1 <= lim0) ? __expf(S[nt][1] - mf0) : 0.f;
                        float p2 = (kcb     <= lim1) ? __expf(S[nt][2] - mf1) : 0.f;
                        float p3 = (kcb + 1 <= lim1) ? __expf(S[nt][3] - mf1) : 0.f;
                        sum0 += p0 + p1; sum1 += p2 + p3;
                        int kc = 16 * ng + 8 * nt + 2 * qd;
                        *(unsigned*)&Ps[R0 * KSTR + kc] = pack_h2(p0, p1);
                        *(unsigned*)&Ps[R1 * KSTR + kc] = pack_h2(p2, p3);
                    }
                    sum0 += __shfl_xor_sync(0xffffffffu, sum0, 1);
                    sum0 += __shfl_xor_sync(0xffffffffu, sum0, 2);
                    sum1 += __shfl_xor_sync(0xffffffffu, sum1, 1);
                    sum1 += __shfl_xor_sync(0xffffffffu, sum1, 2);
                    if (qd == 0) { reds[R0 * 4 + ng] = sum0; reds[R1 * 4 + ng] = sum1; }
                    __syncthreads();

                    if (t < 32) {
                        float mo = m_s[t], mf = mo;
                        #pragma unroll
                        for (int g = 0; g < 4; g++) mf = fmaxf(mf, redm[t * 4 + g]);
                        float sc = __expf(mo - mf);
                        l_s[t] = l_s[t] * sc + reds[t * 4] + reds[t * 4 + 1]
                                             + reds[t * 4 + 2] + reds[t * 4 + 3];
                        m_s[t] = mf;
                        oscs[t] = sc;
                    }
                    __syncthreads();

                    float s0 = oscs[grp],      s1 = oscs[grp + 8];
                    float s2 = oscs[grp + 16], s3 = oscs[grp + 24];
                    #pragma unroll
                    for (int dcx = 0; dcx < 4; dcx++) {
                        Of[dcx][0][0] *= s0; Of[dcx][0][1] *= s0;
                        Of[dcx][0][2] *= s1; Of[dcx][0][3] *= s1;
                        Of[dcx][1][0] *= s2; Of[dcx][1][1] *= s2;
                        Of[dcx][1][2] *= s3; Of[dcx][1][3] *= s3;
                    }
                }

                // ---------- O += P V (dim chunk c-4) ----------
                const int dc = c - 4;
                #pragma unroll
                for (int kk = 0; kk < 4; kk++) {
                    int bkey = kk * 16 + (lane & 7) + 8 * ((lane >> 3) & 1);
                    unsigned ba = kvb + (unsigned)(bkey * KSTR + w * 8) * 2u;
                    unsigned b0, b1;
                    ldsm_x2t(b0, b1, ba);
                    #pragma unroll
                    for (int mt = 0; mt < 2; mt++) {
                        int arow = 16 * mt + (lane & 7) + 8 * ((lane >> 3) & 1);
                        int acol = kk * 16 + 8 * (lane >> 4);
                        unsigned pa = smb + OFF_P + (unsigned)(arow * KSTR + acol) * 2u;
                        unsigned p0, p1, p2, p3;
                        ldsm_x4(p0, p1, p2, p3, pa);
                        mma_f16(Of[dc][mt], p0, p1, p2, p3, b0, b1);
                    }
                }
            }
        }
    }

    __syncthreads();
    size_t obase = ((size_t)split * MAXB + q0) * D;
    #pragma unroll
    for (int dc = 0; dc < 4; dc++) {
        int d = dc * 64 + w * 8 + 2 * qd;
        #pragma unroll
        for (int mt = 0; mt < 2; mt++) {
            int r = 16 * mt + grp;
            *(float2*)&g_Opart[obase + (size_t)r * D + d] =
                make_float2(Of[dc][mt][0], Of[dc][mt][1]);
            *(float2*)&g_Opart[obase + (size_t)(r + 8) * D + d] =
                make_float2(Of[dc][mt][2], Of[dc][mt][3]);
        }
    }
    if (t < 32) {
        g_m[split * MAXB + q0 + t] = m_s[t];
        g_l[split * MAXB + q0 + t] = l_s[t];
    }
}

extern "C" __global__ void combine_kernel(float* __restrict__ out, int Bq)
{
    int idx = blockIdx.x * blockDim.x + threadIdx.x;
    if (idx >= Bq * D) return;
    int q = idx / D;
    int vd = idx - q * D;
    float M = -FLT_MAX;
    #pragma unroll
    for (int s = 0; s < NSPLIT; s++) M = fmaxf(M, g_m[s * MAXB + q]);
    float num = 0.f, den = 0.f;
    #pragma unroll
    for (int s = 0; s < NSPLIT; s++) {
        float wv = __expf(g_m[s * MAXB + q] - M);
        den += wv * g_l[s * MAXB + q];
        num += wv * g_Opart[((size_t)s * MAXB + q) * D + vd];
    }
    out[idx] = num / den;
}

extern "C" void kernel_launch(void* const* d_in, const int* in_sizes, int n_in,
                              void* d_out, int out_size)
{
    const float* q  = (const float*)d_in[0];
    const float* k  = (const float*)d_in[1];
    const float* v  = (const float*)d_in[2];
    const float* Kc = (const float*)d_in[3];
    const float* Vc = (const float*)d_in[4];
    const int* oldp = (const int*)d_in[5];
    int Bq      = in_sizes[0] / D;
    int memrows = in_sizes[3] / D;

    int rows = memrows + Bq + 64;
    if (rows > MAXROWS) rows = MAXROWS;
    long total = (long)rows * 64;
    preconvert<<<(unsigned)((total + 255) / 256), 256>>>(Kc, Vc, k, v, oldp, Bq);

    cudaFuncSetAttribute((const void*)attn_mma,
                         cudaFuncAttributeMaxDynamicSharedMemorySize, SMEM_BYTES);
    dim3 grid(Bq / BM, NSPLIT);
    attn_mma<<<grid, NTHR, SMEM_BYTES>>>(q, oldp, Bq);
    combine_kernel<<<(Bq * D + 255) / 256, 256>>>((float*)d_out, Bq);
}

// round 13
// speedup vs baseline: 9.7998x; 1.5126x over previous
#include <cuda_runtime.h>
#include <cuda_fp16.h>
#include <math.h>
#include <float.h>

#define D      256
#define BM     64
#define BN     64
#define NSPLIT 9
#define NTHR   256
#define QSTR   264
#define KSTR   72
#define MAXB   2048
#define MAXROWS 34944

// ---- smem layout (bytes) ----
#define OFF_Q   0                  // 64 x 264 fp16 = 33792
#define OFF_KV  33792              // 2 slots x 9216
#define KVBUF   9216
#define OFF_P   52224              // 64 x 72 fp16 = 9216
#define OFF_FLT 61440              // floats: m 64, l 64, osc 64, redm 256, reds 256
#define SMEM_BYTES 64256

__device__ float g_Opart[(size_t)NSPLIT * MAXB * D];
__device__ float g_m[NSPLIT * MAXB];
__device__ float g_l[NSPLIT * MAXB];
__device__ __half g_K[(size_t)MAXROWS * D];
__device__ __half g_V[(size_t)MAXROWS * D];

__device__ __forceinline__ unsigned pack_h2(float a, float b) {
    __half2 t = __floats2half2_rn(a, b);
    return *reinterpret_cast<unsigned*>(&t);
}
__device__ __forceinline__ void mma_f16(float* c, unsigned a0, unsigned a1,
                                        unsigned a2, unsigned a3,
                                        unsigned b0, unsigned b1) {
    asm volatile(
        "mma.sync.aligned.m16n8k16.row.col.f32.f16.f16.f32 "
        "{%0,%1,%2,%3}, {%4,%5,%6,%7}, {%8,%9}, {%0,%1,%2,%3};\n"
        : "+f"(c[0]), "+f"(c[1]), "+f"(c[2]), "+f"(c[3])
        : "r"(a0), "r"(a1), "r"(a2), "r"(a3), "r"(b0), "r"(b1));
}
__device__ __forceinline__ void ldsm_x4(unsigned& r0, unsigned& r1, unsigned& r2,
                                        unsigned& r3, unsigned a) {
    asm volatile("ldmatrix.sync.aligned.m8n8.x4.shared.b16 {%0,%1,%2,%3}, [%4];"
                 : "=r"(r0), "=r"(r1), "=r"(r2), "=r"(r3) : "r"(a));
}
__device__ __forceinline__ void ldsm_x2(unsigned& r0, unsigned& r1, unsigned a) {
    asm volatile("ldmatrix.sync.aligned.m8n8.x2.shared.b16 {%0,%1}, [%2];"
                 : "=r"(r0), "=r"(r1) : "r"(a));
}
__device__ __forceinline__ void ldsm_x2t(unsigned& r0, unsigned& r1, unsigned a) {
    asm volatile("ldmatrix.sync.aligned.m8n8.x2.trans.shared.b16 {%0,%1}, [%2];"
                 : "=r"(r0), "=r"(r1) : "r"(a));
}
__device__ __forceinline__ void cpa16(unsigned dst, const void* src) {
    asm volatile("cp.async.cg.shared.global [%0], [%1], 16;" :: "r"(dst), "l"(src));
}
#define CP_COMMIT() asm volatile("cp.async.commit_group;")
#define CP_WAIT0()  asm volatile("cp.async.wait_group 0;")

// async copy of one 64-key x 64-dim fp16 chunk into a slot
__device__ __forceinline__ void stage_async(const __half* G, int kb, int dc,
                                            int t, unsigned base) {
    #pragma unroll
    for (int p = 0; p < 2; p++) {
        int g   = t + NTHR * p;          // 0..511
        int row = g >> 3;
        int c8  = (g & 7) * 8;
        cpa16(base + (unsigned)((row * KSTR + c8) * 2),
              G + (size_t)(kb + row) * D + dc * 64 + c8);
    }
}

// ---- preconvert: fp32 K/V (cache+fresh concat) -> fp16, zero pad ----
extern "C" __global__ void preconvert(const float* __restrict__ Kc,
                                      const float* __restrict__ Vc,
                                      const float* __restrict__ Kn,
                                      const float* __restrict__ Vn,
                                      const int* __restrict__ old_ptr, int Bq)
{
    int old = *old_ptr;
    int nsz = old + Bq;
    int idx = blockIdx.x * blockDim.x + threadIdx.x;   // one per 4 elems
    int row = idx >> 6;
    int c4  = (idx & 63) * 4;
    if (row >= MAXROWS) return;
    size_t o = (size_t)row * D + c4;
    if (row < nsz) {
        const float* ks = (row < old) ? (Kc + (size_t)row * D)
                                      : (Kn + (size_t)(row - old) * D);
        const float* vs = (row < old) ? (Vc + (size_t)row * D)
                                      : (Vn + (size_t)(row - old) * D);
        float4 kv = *(const float4*)(ks + c4);
        float4 vv = *(const float4*)(vs + c4);
        *(uint2*)&g_K[o] = make_uint2(pack_h2(kv.x, kv.y), pack_h2(kv.z, kv.w));
        *(uint2*)&g_V[o] = make_uint2(pack_h2(vv.x, vv.y), pack_h2(vv.z, vv.w));
    } else if (row < nsz + 64) {
        uint2 z = make_uint2(0u, 0u);
        *(uint2*)&g_K[o] = z; *(uint2*)&g_V[o] = z;
    }
}

extern "C" __global__ void __launch_bounds__(NTHR, 2)
attn_mma(const float* __restrict__ Qg, const int* __restrict__ old_ptr, int Bq)
{
    extern __shared__ char smraw[];
    __half* Qs = (__half*)(smraw + OFF_Q);
    __half* Ps = (__half*)(smraw + OFF_P);
    float* m_s  = (float*)(smraw + OFF_FLT);
    float* l_s  = m_s + 64;
    float* oscs = l_s + 64;
    float* redm = oscs + 64;   // [64][4]
    float* reds = redm + 256;  // [64][4]

    const unsigned smb = (unsigned)__cvta_generic_to_shared(smraw);
    const int t    = threadIdx.x;
    const int lane = t & 31;
    const int w    = t >> 5;
    const int grp  = lane >> 2;
    const int qd   = lane & 3;
    const int mg   = w & 1;       // 32-row half
    const int ng   = w >> 1;      // 16-key group

    const int old = *old_ptr;
    const int nsz = old + Bq;
    const int q0  = blockIdx.x * BM;
    const int split = blockIdx.y;

    const int kmax  = min(nsz, old + q0 + BM);
    const int chunk = ((kmax + NSPLIT * BN - 1) / (NSPLIT * BN)) * BN;
    const int kbeg  = split * chunk;
    const int kend  = min(kbeg + chunk, kmax);

    // stage Q (pre-scaled 1/16) as fp16
    #pragma unroll
    for (int p = 0; p < 16; p++) {
        int idx = t + NTHR * p;
        int r   = idx >> 6;
        int c4  = (idx & 63) * 4;
        float4 v = *(const float4*)(Qg + (size_t)(q0 + r) * D + c4);
        *(uint2*)&Qs[r * QSTR + c4] =
            make_uint2(pack_h2(v.x * 0.0625f, v.y * 0.0625f),
                       pack_h2(v.z * 0.0625f, v.w * 0.0625f));
    }
    if (t < 64) { m_s[t] = -FLT_MAX; l_s[t] = 0.f; }

    float Of[4][4][4];
    #pragma unroll
    for (int a = 0; a < 4; a++)
        #pragma unroll
        for (int b = 0; b < 4; b++)
            #pragma unroll
            for (int c = 0; c < 4; c++) Of[a][b][c] = 0.f;

    stage_async(g_K, kbeg, 0, t, smb + OFF_KV);
    CP_COMMIT();

    for (int kb = kbeg; kb < kend; kb += BN) {
        float S[2][2][4];
        #pragma unroll
        for (int mt = 0; mt < 2; mt++)
            #pragma unroll
            for (int nt = 0; nt < 2; nt++)
                #pragma unroll
                for (int i = 0; i < 4; i++) S[mt][nt][i] = 0.f;

        #pragma unroll
        for (int c = 0; c < 8; c++) {
            CP_WAIT0();
            __syncthreads();
            {
                unsigned nb = smb + OFF_KV + ((unsigned)((c + 1) & 1)) * KVBUF;
                if (c < 3)       stage_async(g_K, kb, c + 1, t, nb);
                else if (c == 3) stage_async(g_V, kb, 0, t, nb);
                else if (c < 7)  stage_async(g_V, kb, c - 3, t, nb);
                else if (kb + BN < kend)
                                 stage_async(g_K, kb + BN, 0, t, nb);
            }
            CP_COMMIT();

            const unsigned kvb = smb + OFF_KV + ((unsigned)(c & 1)) * KVBUF;

            if (c < 4) {
                // ---------- S += Q K^T (dim chunk c) ----------
                const int dc = c;
                #pragma unroll
                for (int ks = 0; ks < 4; ks++) {
                    unsigned b0[2], b1[2];
                    #pragma unroll
                    for (int nt = 0; nt < 2; nt++) {
                        int bkey = 16 * ng + 8 * nt + (lane & 7);
                        int bcol = ks * 16 + 8 * ((lane >> 3) & 1);
                        ldsm_x2(b0[nt], b1[nt], kvb + (unsigned)(bkey * KSTR + bcol) * 2u);
                    }
                    #pragma unroll
                    for (int mt = 0; mt < 2; mt++) {
                        int arow = 32 * mg + 16 * mt + (lane & 7) + 8 * ((lane >> 3) & 1);
                        int acol = dc * 64 + ks * 16 + 8 * (lane >> 4);
                        unsigned a0, a1, a2, a3;
                        ldsm_x4(a0, a1, a2, a3,
                                smb + OFF_Q + (unsigned)(arow * QSTR + acol) * 2u);
                        #pragma unroll
                        for (int nt = 0; nt < 2; nt++)
                            mma_f16(S[mt][nt], a0, a1, a2, a3, b0[nt], b1[nt]);
                    }
                }
            } else {
                if (c == 4) {
                    // ---------- online softmax ----------
                    #pragma unroll
                    for (int mt = 0; mt < 2; mt++) {
                        const int R0 = 32 * mg + 16 * mt + grp, R1 = R0 + 8;
                        const int lim0 = old + q0 + R0, lim1 = old + q0 + R1;
                        float mx0 = -FLT_MAX, mx1 = -FLT_MAX;
                        #pragma unroll
                        for (int nt = 0; nt < 2; nt++) {
                            int kcb = kb + 16 * ng + 8 * nt + 2 * qd;
                            mx0 = fmaxf(mx0, fmaxf((kcb     <= lim0) ? S[mt][nt][0] : -FLT_MAX,
                                                   (kcb + 1 <= lim0) ? S[mt][nt][1] : -FLT_MAX));
                            mx1 = fmaxf(mx1, fmaxf((kcb     <= lim1) ? S[mt][nt][2] : -FLT_MAX,
                                                   (kcb + 1 <= lim1) ? S[mt][nt][3] : -FLT_MAX));
                        }
                        mx0 = fmaxf(mx0, __shfl_xor_sync(0xffffffffu, mx0, 1));
                        mx0 = fmaxf(mx0, __shfl_xor_sync(0xffffffffu, mx0, 2));
                        mx1 = fmaxf(mx1, __shfl_xor_sync(0xffffffffu, mx1, 1));
                        mx1 = fmaxf(mx1, __shfl_xor_sync(0xffffffffu, mx1, 2));
                        if (qd == 0) { redm[R0 * 4 + ng] = mx0; redm[R1 * 4 + ng] = mx1; }
                    }
                    __syncthreads();

                    #pragma unroll
                    for (int mt = 0; mt < 2; mt++) {
                        const int R0 = 32 * mg + 16 * mt + grp, R1 = R0 + 8;
                        const int lim0 = old + q0 + R0, lim1 = old + q0 + R1;
                        float mf0 = m_s[R0], mf1 = m_s[R1];
                        #pragma unroll
                        for (int g = 0; g < 4; g++) {
                            mf0 = fmaxf(mf0, redm[R0 * 4 + g]);
                            mf1 = fmaxf(mf1, redm[R1 * 4 + g]);
                        }
                        float sum0 = 0.f, sum1 = 0.f;
                        #pragma unroll
                        for (int nt = 0; nt < 2; nt++) {
                            int kcb = kb + 16 * ng + 8 * nt + 2 * qd;
                            float p0 = (kcb     <= lim0) ? __expf(S[mt][nt][0] - mf0) : 0.f;
                            float p1 = (kcb + 1 <= lim0) ? __expf(S[mt][nt][1] - mf0) : 0.f;
                            float p2 = (kcb     <= lim1) ? __expf(S[mt][nt][2] - mf1) : 0.f;
                            float p3 = (kcb + 1 <= lim1) ? __expf(S[mt][nt][3] - mf1) : 0.f;
                            sum0 += p0 + p1; sum1 += p2 + p3;
                            int kc = 16 * ng + 8 * nt + 2 * qd;
                            *(unsigned*)&Ps[R0 * KSTR + kc] = pack_h2(p0, p1);
                            *(unsigned*)&Ps[R1 * KSTR + kc] = pack_h2(p2, p3);
                        }
                        sum0 += __shfl_xor_sync(0xffffffffu, sum0, 1);
                        sum0 += __shfl_xor_sync(0xffffffffu, sum0, 2);
                        sum1 += __shfl_xor_sync(0xffffffffu, sum1, 1);
                        sum1 += __shfl_xor_sync(0xffffffffu, sum1, 2);
                        if (qd == 0) { reds[R0 * 4 + ng] = sum0; reds[R1 * 4 + ng] = sum1; }
                    }
                    __syncthreads();

                    if (t < 64) {
                        float mo = m_s[t], mf = mo;
                        #pragma unroll
                        for (int g = 0; g < 4; g++) mf = fmaxf(mf, redm[t * 4 + g]);
                        float sc = __expf(mo - mf);
                        l_s[t] = l_s[t] * sc + reds[t * 4] + reds[t * 4 + 1]
                                             + reds[t * 4 + 2] + reds[t * 4 + 3];
                        m_s[t] = mf;
                        oscs[t] = sc;
                    }
                    __syncthreads();

                    #pragma unroll
                    for (int mt2 = 0; mt2 < 4; mt2++) {
                        float sa = oscs[16 * mt2 + grp];
                        float sb = oscs[16 * mt2 + grp + 8];
                        #pragma unroll
                        for (int dcx = 0; dcx < 4; dcx++) {
                            Of[dcx][mt2][0] *= sa; Of[dcx][mt2][1] *= sa;
                            Of[dcx][mt2][2] *= sb; Of[dcx][mt2][3] *= sb;
                        }
                    }
                }

                // ---------- O += P V (dim chunk c-4) ----------
                const int dc = c - 4;
                #pragma unroll
                for (int kk = 0; kk < 4; kk++) {
                    int bkey = kk * 16 + (lane & 7) + 8 * ((lane >> 3) & 1);
                    unsigned b0, b1;
                    ldsm_x2t(b0, b1, kvb + (unsigned)(bkey * KSTR + w * 8) * 2u);
                    #pragma unroll
                    for (int mt2 = 0; mt2 < 4; mt2++) {
                        int arow = 16 * mt2 + (lane & 7) + 8 * ((lane >> 3) & 1);
                        int acol = kk * 16 + 8 * (lane >> 4);
                        unsigned p0, p1, p2, p3;
                        ldsm_x4(p0, p1, p2, p3,
                                smb + OFF_P + (unsigned)(arow * KSTR + acol) * 2u);
                        mma_f16(Of[dc][mt2], p0, p1, p2, p3, b0, b1);
                    }
                }
            }
        }
    }

    __syncthreads();
    size_t obase = ((size_t)split * MAXB + q0) * D;
    #pragma unroll
    for (int dc = 0; dc < 4; dc++) {
        int d = dc * 64 + w * 8 + 2 * qd;
        #pragma unroll
        for (int mt2 = 0; mt2 < 4; mt2++) {
            int r = 16 * mt2 + grp;
            *(float2*)&g_Opart[obase + (size_t)r * D + d] =
                make_float2(Of[dc][mt2][0], Of[dc][mt2][1]);
            *(float2*)&g_Opart[obase + (size_t)(r + 8) * D + d] =
                make_float2(Of[dc][mt2][2], Of[dc][mt2][3]);
        }
    }
    if (t < 64) {
        g_m[split * MAXB + q0 + t] = m_s[t];
        g_l[split * MAXB + q0 + t] = l_s[t];
    }
}

extern "C" __global__ void combine_kernel(float* __restrict__ out, int Bq)
{
    int idx = blockIdx.x * blockDim.x + threadIdx.x;
    if (idx >= Bq * D) return;
    int q = idx / D;
    int vd = idx - q * D;
    float M = -FLT_MAX;
    #pragma unroll
    for (int s = 0; s < NSPLIT; s++) M = fmaxf(M, g_m[s * MAXB + q]);
    float num = 0.f, den = 0.f;
    #pragma unroll
    for (int s = 0; s < NSPLIT; s++) {
        float wv = __expf(g_m[s * MAXB + q] - M);
        den += wv * g_l[s * MAXB + q];
        num += wv * g_Opart[((size_t)s * MAXB + q) * D + vd];
    }
    out[idx] = num / den;
}

extern "C" void kernel_launch(void* const* d_in, const int* in_sizes, int n_in,
                              void* d_out, int out_size)
{
    const float* q  = (const float*)d_in[0];
    const float* k  = (const float*)d_in[1];
    const float* v  = (const float*)d_in[2];
    const float* Kc = (const float*)d_in[3];
    const float* Vc = (const float*)d_in[4];
    const int* oldp = (const int*)d_in[5];
    int Bq      = in_sizes[0] / D;
    int memrows = in_sizes[3] / D;

    int rows = memrows + Bq + 64;
    if (rows > MAXROWS) rows = MAXROWS;
    long total = (long)rows * 64;
    preconvert<<<(unsigned)((total + 255) / 256), 256>>>(Kc, Vc, k, v, oldp, Bq);

    cudaFuncSetAttribute((const void*)attn_mma,
                         cudaFuncAttributeMaxDynamicSharedMemorySize, SMEM_BYTES);
    dim3 grid(Bq / BM, NSPLIT);
    attn_mma<<<grid, NTHR, SMEM_BYTES>>>(q, oldp, Bq);
    combine_kernel<<<(Bq * D + 255) / 256, 256>>>((float*)d_out, Bq);
}